// round 4
// baseline (speedup 1.0000x reference)
#include <cuda_runtime.h>
#include <cstdint>

// ---------------------------------------------------------------------------
// GATConv GB300 (sm_103, mma.sync path): N=100000, E=1600000, H=4, D=32
//   K0   zero counters
//   K0b  w_eh[k][h]
//   K0c  B' fragment-major: [Bh;Bh;Bl] of [W_fc|W_res]^T  (K'=384, N=256)
//   K1   mma.sync tf32 GEMM, K-augmented 3xTF32: feat / out(+bias)
//   K2   a_src/a_dst per node (warp per node)
//   K3   histogram count[dst]
//   K4   exclusive scan -> offsets
//   K6   edge logits + inline CSR fill -> {e4}, {src} in CSR order
//   K7   warp-per-node SINGLE-PASS softmax + gather-aggregate
// ---------------------------------------------------------------------------

#define N_NODES 100000
#define N_EDGES 1600000
#define NEG_SLOPE 0.2f

__device__ __align__(16) float  d_feat[N_NODES * 128];
__device__ __align__(16) float  d_asrc[N_NODES * 4];
__device__ __align__(16) float  d_adst[N_NODES * 4];
__device__ __align__(16) float4 d_pe[N_EDGES];
__device__ __align__(16) int    d_ps[N_EDGES];
__device__ __align__(16) float  d_weh[64];            // [k=16][h=4]
__device__ __align__(16) float  d_Bfrag[48 * 2048];   // frag-major B' (K'=384,N=256)
__device__ __align__(16) int    d_count[N_NODES + 4];
__device__ __align__(16) int    d_count2[N_NODES];
__device__ __align__(16) int    d_offsets[N_NODES + 1];

__device__ __forceinline__ float tf32r(float x) {
    uint32_t r;
    asm("cvt.rna.tf32.f32 %0, %1;" : "=r"(r) : "f"(x));
    return __uint_as_float(r);
}

__device__ __forceinline__ void mma_tf32(float* c, const float4& a, const float2& b) {
    const uint32_t* ap = reinterpret_cast<const uint32_t*>(&a);
    const uint32_t* bp = reinterpret_cast<const uint32_t*>(&b);
    asm volatile(
        "mma.sync.aligned.m16n8k8.row.col.f32.tf32.tf32.f32 "
        "{%0,%1,%2,%3}, {%4,%5,%6,%7}, {%8,%9}, {%0,%1,%2,%3};"
        : "+f"(c[0]), "+f"(c[1]), "+f"(c[2]), "+f"(c[3])
        : "r"(ap[0]), "r"(ap[1]), "r"(ap[2]), "r"(ap[3]),
          "r"(bp[0]), "r"(bp[1]));
}

// ---------------- K0: zero counters ----------------
__global__ void k_init() {
    int i = blockIdx.x * blockDim.x + threadIdx.x;
    int total = (N_NODES + 4) + N_NODES;
    for (; i < total; i += gridDim.x * blockDim.x) {
        if (i < N_NODES + 4) d_count[i] = 0;
        else d_count2[i - (N_NODES + 4)] = 0;
    }
}

// ---------------- K0b: w_eh ----------------
__global__ void k_weh(const float* __restrict__ W_edge,
                      const float* __restrict__ attn_edge) {
    int t = threadIdx.x;
    if (t >= 64) return;
    int k = t >> 2, h = t & 3;
    float s = 0.f;
    #pragma unroll
    for (int d = 0; d < 32; d++)
        s += W_edge[k * 128 + h * 32 + d] * attn_edge[h * 32 + d];
    d_weh[k * 4 + h] = s;
}

// ---------------- K0c: B' in mma-fragment-major layout ----------------
// element i: reg=i&1, lane=(i>>1)&31, ntg=(i>>6)&31, kt=i>>11 (0..47)
// fragment coords: k = (kt%16)*8 + (lane&3) + reg*4 ; n = ntg*8 + (lane>>2)
// regions: kt<16 -> Bh, kt<32 -> Bh, else Bl
__global__ void k_bfrag(const float* __restrict__ W_fc,
                        const float* __restrict__ W_res) {
    int i = blockIdx.x * blockDim.x + threadIdx.x;
    if (i >= 48 * 2048) return;
    int reg = i & 1;
    int lane = (i >> 1) & 31;
    int ntg = (i >> 6) & 31;
    int kt = i >> 11;
    int k = (kt & 15) * 8 + (lane & 3) + reg * 4;
    int n = ntg * 8 + (lane >> 2);
    float w = (n < 128) ? W_fc[k * 128 + n] : W_res[k * 128 + (n - 128)];
    float h = tf32r(w);
    d_Bfrag[i] = (kt >= 32) ? tf32r(w - h) : h;
}

// ---------------- K1: mma.sync tf32 GEMM, K'=384, BM=128 BN=128 BK=32 ------
// warps: warp_m = wid&1 (64 rows), warp_n = wid>>1 (32 cols)
// A regions per kb (0..11): kb<4 -> Ah, kb<8 -> Al, else Ah ; colbase=(kb&3)*32
__global__ __launch_bounds__(256, 1)
void k_gemm_mma(const float* __restrict__ A, float* __restrict__ out,
                const float* __restrict__ bias, int M) {
    extern __shared__ float sm[];
    float* As = sm;           // 2 x 4096 floats
    float* Bs = sm + 8192;    // 2 x 4096 floats

    int tid = threadIdx.x, wid = tid >> 5, lane = tid & 31;
    int warp_m = wid & 1, warp_n = wid >> 1;
    int n0 = blockIdx.x * 128;
    int row0 = blockIdx.y * 128;

    int r = tid >> 1;                 // A row this thread loads (0..127)
    int cb = (tid & 1) * 16;          // A col base within BK

    float acc[4][4][4];
    #pragma unroll
    for (int i = 0; i < 4; i++)
        #pragma unroll
        for (int j = 0; j < 4; j++)
            #pragma unroll
            for (int q = 0; q < 4; q++) acc[i][j][q] = 0.f;

    float4 a_st[4];
    float4 b_st[4];

    auto load_stage = [&](int kb) {
        const float* ap = A + (size_t)(row0 + r) * 128 + (kb & 3) * 32 + cb;
        bool ok = (row0 + r) < M;
        #pragma unroll
        for (int q = 0; q < 4; q++)
            a_st[q] = ok ? *(const float4*)(ap + q * 4)
                         : make_float4(0.f, 0.f, 0.f, 0.f);
        #pragma unroll
        for (int ks = 0; ks < 4; ks++) {
            int gbase = ((kb * 4 + ks) * 32 + (n0 >> 3)) * 64;
            b_st[ks] = *(const float4*)(d_Bfrag + gbase + tid * 4);
        }
    };

    auto store_stage = [&](int kb, int buf) {
        int region = kb >> 2;   // 0:h 1:l 2:h
        float* Ab = As + buf * 4096;
        int rr = r & 15, mt = r >> 4;
        #pragma unroll
        for (int q = 0; q < 4; q++) {
            float vv[4] = {a_st[q].x, a_st[q].y, a_st[q].z, a_st[q].w};
            #pragma unroll
            for (int j = 0; j < 4; j++) {
                int c = cb + q * 4 + j;           // 0..31
                float v = vv[j];
                float h = tf32r(v);
                float val = (region == 1) ? tf32r(v - h) : h;
                int ks = c >> 3, cc = c & 7;
                int lane2 = (rr & 7) * 4 + (cc & 3);
                int reg = ((rr >> 3) & 1) | ((cc >> 2) << 1);
                Ab[(ks * 8 + mt) * 128 + lane2 * 4 + reg] = val;
            }
        }
        float* Bb = Bs + buf * 4096;
        #pragma unroll
        for (int ks = 0; ks < 4; ks++)
            *(float4*)(Bb + ks * 1024 + tid * 4) = b_st[ks];
    };

    auto compute = [&](int buf) {
        const float* Ab = As + buf * 4096;
        const float* Bb = Bs + buf * 4096;
        #pragma unroll
        for (int ks = 0; ks < 4; ks++) {
            float4 af[4];
            float2 bf[4];
            #pragma unroll
            for (int mt = 0; mt < 4; mt++)
                af[mt] = *(const float4*)(Ab + (ks * 8 + warp_m * 4 + mt) * 128 + lane * 4);
            #pragma unroll
            for (int nt = 0; nt < 4; nt++)
                bf[nt] = *(const float2*)(Bb + (ks * 16 + warp_n * 4 + nt) * 64 + lane * 2);
            #pragma unroll
            for (int mt = 0; mt < 4; mt++)
                #pragma unroll
                for (int nt = 0; nt < 4; nt++)
                    mma_tf32(acc[mt][nt], af[mt], bf[nt]);
        }
    };

    load_stage(0);
    store_stage(0, 0);
    __syncthreads();
    for (int kb = 0; kb < 12; kb++) {
        int buf = kb & 1;
        if (kb + 1 < 12) load_stage(kb + 1);
        compute(buf);
        if (kb + 1 < 12) store_stage(kb + 1, buf ^ 1);
        __syncthreads();
    }

    // epilogue
    int g = lane >> 2, t = lane & 3;
    #pragma unroll
    for (int mt = 0; mt < 4; mt++) {
        int row = row0 + warp_m * 64 + mt * 16 + g;
        #pragma unroll
        for (int nt = 0; nt < 4; nt++) {
            int col = warp_n * 32 + nt * 8 + t * 2;   // col within N-block
            float* c = acc[mt][nt];
            if (n0 == 0) {
                if (row < M)
                    *(float2*)(d_feat + (size_t)row * 128 + col) =
                        make_float2(c[0], c[1]);
                if (row + 8 < M)
                    *(float2*)(d_feat + (size_t)(row + 8) * 128 + col) =
                        make_float2(c[2], c[3]);
            } else {
                float2 bz = *(const float2*)(bias + col);
                if (row < M)
                    *(float2*)(out + (size_t)row * 128 + col) =
                        make_float2(c[0] + bz.x, c[1] + bz.y);
                if (row + 8 < M)
                    *(float2*)(out + (size_t)(row + 8) * 128 + col) =
                        make_float2(c[2] + bz.x, c[3] + bz.y);
            }
        }
    }
}

// ---------------- K2: per-node attention logits (warp per node) ------------
__global__ void k_attn_node(const float* __restrict__ attn_src,
                            const float* __restrict__ attn_dst) {
    int warp = (blockIdx.x * blockDim.x + threadIdx.x) >> 5;
    int lane = threadIdx.x & 31;
    if (warp >= N_NODES) return;
    int n = warp;

    float4 fv = *(const float4*)(d_feat + (size_t)n * 128 + lane * 4);
    float4 as = *(const float4*)(attn_src + lane * 4);
    float4 ad = *(const float4*)(attn_dst + lane * 4);

    float ps = fv.x * as.x + fv.y * as.y + fv.z * as.z + fv.w * as.w;
    float pd = fv.x * ad.x + fv.y * ad.y + fv.z * ad.z + fv.w * ad.w;

    #pragma unroll
    for (int o = 1; o < 8; o <<= 1) {
        ps += __shfl_xor_sync(0xffffffffu, ps, o);
        pd += __shfl_xor_sync(0xffffffffu, pd, o);
    }
    if ((lane & 7) == 0) {
        int h = lane >> 3;
        d_asrc[n * 4 + h] = ps;
        d_adst[n * 4 + h] = pd;
    }
}

// ---------------- K3: histogram ----------------
__global__ void k_hist(const int* __restrict__ dst) {
    int i4 = (blockIdx.x * blockDim.x + threadIdx.x) * 4;
    if (i4 + 3 < N_EDGES) {
        int4 d = *(const int4*)(dst + i4);
        atomicAdd(&d_count[d.x], 1);
        atomicAdd(&d_count[d.y], 1);
        atomicAdd(&d_count[d.z], 1);
        atomicAdd(&d_count[d.w], 1);
    } else {
        for (int i = i4; i < N_EDGES; i++) atomicAdd(&d_count[dst[i]], 1);
    }
}

// ---------------- K4: single-block exclusive scan ----------------
__global__ void k_scan() {
    __shared__ int wsum[32];
    int tid = threadIdx.x;
    int lane = tid & 31, wid = tid >> 5;
    int running = 0;
    if (tid == 0) d_offsets[0] = 0;
    for (int b = 0; b < N_NODES; b += 4096) {
        int i0 = b + tid * 4;
        int v0 = 0, v1 = 0, v2 = 0, v3 = 0;
        if (i0 + 3 < N_NODES) {
            int4 v = *(const int4*)&d_count[i0];
            v0 = v.x; v1 = v.y; v2 = v.z; v3 = v.w;
        } else {
            if (i0 + 0 < N_NODES) v0 = d_count[i0 + 0];
            if (i0 + 1 < N_NODES) v1 = d_count[i0 + 1];
            if (i0 + 2 < N_NODES) v2 = d_count[i0 + 2];
            if (i0 + 3 < N_NODES) v3 = d_count[i0 + 3];
        }
        int p0 = v0, p1 = p0 + v1, p2 = p1 + v2, p3 = p2 + v3;
        int x = p3;
        #pragma unroll
        for (int o = 1; o < 32; o <<= 1) {
            int t = __shfl_up_sync(0xffffffffu, x, o);
            if (lane >= o) x += t;
        }
        if (lane == 31) wsum[wid] = x;
        __syncthreads();
        if (wid == 0) {
            int y = wsum[lane];
            #pragma unroll
            for (int o = 1; o < 32; o <<= 1) {
                int t = __shfl_up_sync(0xffffffffu, y, o);
                if (lane >= o) y += t;
            }
            wsum[lane] = y;
        }
        __syncthreads();
        int warpoff = (wid > 0) ? wsum[wid - 1] : 0;
        int bs = running + warpoff + (x - p3);
        if (i0 + 0 < N_NODES) d_offsets[i0 + 1] = bs + p0;
        if (i0 + 1 < N_NODES) d_offsets[i0 + 2] = bs + p1;
        if (i0 + 2 < N_NODES) d_offsets[i0 + 3] = bs + p2;
        if (i0 + 3 < N_NODES) d_offsets[i0 + 4] = bs + p3;
        int tot = wsum[31];
        __syncthreads();
        running += tot;
    }
}

// ---------------- K6: edge logits + inline CSR fill ----------------
__global__ void k_edge_e(const float* __restrict__ edge_inputs,
                         const int* __restrict__ src,
                         const int* __restrict__ dst) {
    __shared__ float sweh[64];
    if (threadIdx.x < 64) sweh[threadIdx.x] = d_weh[threadIdx.x];
    __syncthreads();

    int e = blockIdx.x * blockDim.x + threadIdx.x;
    if (e >= N_EDGES) return;

    int s = src[e];
    int d = dst[e];
    float4 as = *(const float4*)(d_asrc + s * 4);
    float4 ad = *(const float4*)(d_adst + d * 4);

    float ae[4] = {0.f, 0.f, 0.f, 0.f};
    const float* ep = edge_inputs + (size_t)e * 16;
    #pragma unroll
    for (int kq = 0; kq < 4; kq++) {
        float4 ev = *(const float4*)(ep + kq * 4);
        float efs[4] = {ev.x, ev.y, ev.z, ev.w};
        #pragma unroll
        for (int kk = 0; kk < 4; kk++) {
            int k = kq * 4 + kk;
            #pragma unroll
            for (int h = 0; h < 4; h++) ae[h] += efs[kk] * sweh[k * 4 + h];
        }
    }

    float av[4] = {as.x, as.y, as.z, as.w};
    float dv[4] = {ad.x, ad.y, ad.z, ad.w};
    float res[4];
    #pragma unroll
    for (int h = 0; h < 4; h++) {
        float v = av[h] + dv[h] + ae[h];
        res[h] = (v > 0.f) ? v : NEG_SLOPE * v;
    }

    int p = d_offsets[d] + atomicAdd(&d_count2[d], 1);
    d_pe[p] = make_float4(res[0], res[1], res[2], res[3]);
    d_ps[p] = s;
}

// ---------------- K7: warp-per-node single-pass softmax + aggregate --------
__global__ void k_aggregate(float* __restrict__ out) {
    int warp = (blockIdx.x * blockDim.x + threadIdx.x) >> 5;
    int lane = threadIdx.x & 31;
    if (warp >= N_NODES) return;
    int n = warp;

    int begin = d_offsets[n];
    int deg = d_offsets[n + 1] - begin;
    if (deg == 0) return;

    int hl = lane >> 3;
    float s0 = 0.f, s1 = 0.f, s2 = 0.f, s3 = 0.f;
    float acc0 = 0.f, acc1 = 0.f, acc2 = 0.f, acc3 = 0.f;

    for (int b = 0; b < deg; b += 32) {
        int j = b + lane;
        float4 w4 = make_float4(0.f, 0.f, 0.f, 0.f);
        int sn = 0;
        if (j < deg) {
            float4 ev = d_pe[begin + j];
            sn = d_ps[begin + j];
            w4.x = __expf(ev.x);
            w4.y = __expf(ev.y);
            w4.z = __expf(ev.z);
            w4.w = __expf(ev.w);
        }
        s0 += w4.x; s1 += w4.y; s2 += w4.z; s3 += w4.w;
        int cnt = min(32, deg - b);
        #pragma unroll 4
        for (int k = 0; k < cnt; k++) {
            float wx = __shfl_sync(0xffffffffu, w4.x, k);
            float wy = __shfl_sync(0xffffffffu, w4.y, k);
            float wz = __shfl_sync(0xffffffffu, w4.z, k);
            float ww = __shfl_sync(0xffffffffu, w4.w, k);
            int snk = __shfl_sync(0xffffffffu, sn, k);
            float w = (hl < 2) ? (hl == 0 ? wx : wy) : (hl == 2 ? wz : ww);
            float4 fv = *(const float4*)(d_feat + (size_t)snk * 128 + lane * 4);
            acc0 += fv.x * w;
            acc1 += fv.y * w;
            acc2 += fv.z * w;
            acc3 += fv.w * w;
        }
    }
    #pragma unroll
    for (int o = 16; o > 0; o >>= 1) {
        s0 += __shfl_xor_sync(0xffffffffu, s0, o);
        s1 += __shfl_xor_sync(0xffffffffu, s1, o);
        s2 += __shfl_xor_sync(0xffffffffu, s2, o);
        s3 += __shfl_xor_sync(0xffffffffu, s3, o);
    }
    float s = (hl < 2) ? (hl == 0 ? s0 : s1) : (hl == 2 ? s2 : s3);
    float inv = 1.f / s;

    float4* op = (float4*)(out + (size_t)n * 128 + lane * 4);
    float4 ov = *op;  // residual + bias from GEMM epilogue
    ov.x += acc0 * inv; ov.y += acc1 * inv;
    ov.z += acc2 * inv; ov.w += acc3 * inv;
    *op = ov;
}

// ---------------------------------------------------------------------------
extern "C" void kernel_launch(void* const* d_in, const int* in_sizes, int n_in,
                              void* d_out, int out_size) {
    const float* node_inputs = (const float*)d_in[0];
    const float* edge_inputs = (const float*)d_in[1];
    const int*   src         = (const int*)d_in[2];
    const int*   dst         = (const int*)d_in[3];
    const float* W_fc        = (const float*)d_in[4];
    const float* attn_src_p  = (const float*)d_in[5];
    const float* attn_dst_p  = (const float*)d_in[6];
    const float* W_edge      = (const float*)d_in[7];
    const float* attn_edge_p = (const float*)d_in[8];
    const float* W_res       = (const float*)d_in[9];
    const float* bias_p      = (const float*)d_in[10];
    float* out = (float*)d_out;

    static int smem_set = 0;
    if (!smem_set) {
        cudaFuncSetAttribute(k_gemm_mma,
                             cudaFuncAttributeMaxDynamicSharedMemorySize,
                             65536);
        smem_set = 1;
    }

    k_init<<<256, 256>>>();
    k_weh<<<1, 64>>>(W_edge, attn_edge_p);
    k_bfrag<<<(48 * 2048 + 255) / 256, 256>>>(W_fc, W_res);
    {
        dim3 grid(2, 782);
        k_gemm_mma<<<grid, 256, 65536>>>(node_inputs, out, bias_p, N_NODES);
    }
    k_attn_node<<<(N_NODES * 32 + 255) / 256, 256>>>(attn_src_p, attn_dst_p);
    k_hist<<<(N_EDGES / 4 + 255) / 256, 256>>>(dst);
    k_scan<<<1, 1024>>>();
    k_edge_e<<<(N_EDGES + 255) / 256, 256>>>(edge_inputs, src, dst);
    k_aggregate<<<(N_NODES * 32 + 255) / 256, 256>>>(out);
}

// round 5
// speedup vs baseline: 1.4080x; 1.4080x over previous
#include <cuda_runtime.h>
#include <cuda_bf16.h>
#include <cstdint>

// ---------------------------------------------------------------------------
// GATConv GB300 (sm_103): N=100000, E=1600000, H=4, D=32
//   K0   zero counters
//   K0b  w_eh[k][h]
//   K0c  B fragments (bf16 hi/lo) of [W_fc|W_res], mma-fragment-major
//   K1   mma.sync bf16 GEMM, 3-term split (AhBh+AlBh+AhBl):
//        feat / out(+bias); a_src/a_dst fused in epilogue
//   K3   histogram count[dst]
//   K4   exclusive scan -> offsets
//   K6   edge logits + inline CSR fill -> {e4},{src} in CSR order
//   K7   warp-per-node SINGLE-PASS softmax + gather-aggregate
// ---------------------------------------------------------------------------

#define N_NODES 100000
#define N_EDGES 1600000
#define NEG_SLOPE 0.2f
#define NT_TILES ((N_NODES + 63) / 64)

__device__ __align__(16) float  d_feat[N_NODES * 128];
__device__ __align__(16) float  d_asrc[N_NODES * 4];
__device__ __align__(16) float  d_adst[N_NODES * 4];
__device__ __align__(16) float4 d_pe[N_EDGES];
__device__ __align__(16) int    d_ps[N_EDGES];
__device__ __align__(16) float  d_weh[64];        // [k=16][h=4]
__device__ __align__(16) uint2  d_Bf[16384];      // [term][kt8][ntg32][lane32]
__device__ __align__(16) int    d_count[N_NODES + 4];
__device__ __align__(16) int    d_count2[N_NODES];
__device__ __align__(16) int    d_offsets[N_NODES + 1];

// ---------------- helpers ----------------
__device__ __forceinline__ uint32_t smem_to_u32(const void* p) {
    uint32_t a;
    asm("{ .reg .u64 t; cvta.to.shared.u64 t, %1; cvt.u32.u64 %0, t; }"
        : "=r"(a) : "l"(p));
    return a;
}
__device__ __forceinline__ float bfr(float x) {
    return __bfloat162float(__float2bfloat16(x));
}
__device__ __forceinline__ uint32_t pbf2(float a, float b) {
    uint16_t ua = __bfloat16_as_ushort(__float2bfloat16(a));
    uint16_t ub = __bfloat16_as_ushort(__float2bfloat16(b));
    return (uint32_t)ua | ((uint32_t)ub << 16);
}
__device__ __forceinline__ void ldsm4(uint32_t* a, uint32_t addr) {
    asm volatile("ldmatrix.sync.aligned.m8n8.x4.shared.b16 {%0,%1,%2,%3}, [%4];"
        : "=r"(a[0]), "=r"(a[1]), "=r"(a[2]), "=r"(a[3]) : "r"(addr));
}
__device__ __forceinline__ void mma_bf16(float* c, const uint32_t* a,
                                         uint32_t b0, uint32_t b1) {
    asm volatile(
        "mma.sync.aligned.m16n8k16.row.col.f32.bf16.bf16.f32 "
        "{%0,%1,%2,%3}, {%4,%5,%6,%7}, {%8,%9}, {%0,%1,%2,%3};"
        : "+f"(c[0]), "+f"(c[1]), "+f"(c[2]), "+f"(c[3])
        : "r"(a[0]), "r"(a[1]), "r"(a[2]), "r"(a[3]), "r"(b0), "r"(b1));
}

// ---------------- K0: zero counters ----------------
__global__ void k_init() {
    int i = blockIdx.x * blockDim.x + threadIdx.x;
    int total = (N_NODES + 4) + N_NODES;
    for (; i < total; i += gridDim.x * blockDim.x) {
        if (i < N_NODES + 4) d_count[i] = 0;
        else d_count2[i - (N_NODES + 4)] = 0;
    }
}

// ---------------- K0b: w_eh ----------------
__global__ void k_weh(const float* __restrict__ W_edge,
                      const float* __restrict__ attn_edge) {
    int t = threadIdx.x;
    if (t >= 64) return;
    int k = t >> 2, h = t & 3;
    float s = 0.f;
    #pragma unroll
    for (int d = 0; d < 32; d++)
        s += W_edge[k * 128 + h * 32 + d] * attn_edge[h * 32 + d];
    d_weh[k * 4 + h] = s;
}

// ---------------- K0c: B fragments hi/lo ----------------
// i = term*8192 + kt*1024 + ntg*32 + lane
// frag elem (m16n8k16 B): reg0 k = kt*16+(lane%4)*2+{0,1}, reg1 k += 8; n = ntg*8 + lane/4
__global__ void k_bsplit(const float* __restrict__ W_fc,
                         const float* __restrict__ W_res) {
    int i = blockIdx.x * blockDim.x + threadIdx.x;
    if (i >= 16384) return;
    int lane = i & 31, ntg = (i >> 5) & 31, kt = (i >> 10) & 7, term = i >> 13;
    int n = ntg * 8 + (lane >> 2);
    int kb = kt * 16 + (lane & 3) * 2;
    float w[4];
    #pragma unroll
    for (int j = 0; j < 4; j++) {
        int k = kb + (j >> 1) * 8 + (j & 1);
        w[j] = (n < 128) ? W_fc[k * 128 + n] : W_res[k * 128 + n - 128];
    }
    uint32_t r0, r1;
    if (term == 0) {
        r0 = pbf2(w[0], w[1]);
        r1 = pbf2(w[2], w[3]);
    } else {
        r0 = pbf2(w[0] - bfr(w[0]), w[1] - bfr(w[1]));
        r1 = pbf2(w[2] - bfr(w[2]), w[3] - bfr(w[3]));
    }
    d_Bf[i] = make_uint2(r0, r1);
}

// ---------------- K1: bf16x3 mma GEMM ----------------
// smem: [0,131072) B frags (term0 hi, term1 lo); [131072, 196608) A tiles:
//   [buf][term][64 rows][16 chunks x 16B], chunk phys = c ^ (r&7)
#define SMEM_A_OFF 131072
#define GEMM_SMEM  196608

__device__ __forceinline__ void fillA(const float* __restrict__ A, int row0,
                                      int buf, char* smA, int tid, int M) {
    int r = tid >> 2, cq = tid & 3;
    int grow = row0 + r;
    float4 v[8];
    if (grow < M) {
        const float4* ap = (const float4*)(A + (size_t)grow * 128 + cq * 32);
        #pragma unroll
        for (int q = 0; q < 8; q++) v[q] = __ldg(ap + q);
    } else {
        #pragma unroll
        for (int q = 0; q < 8; q++) v[q] = make_float4(0.f, 0.f, 0.f, 0.f);
    }
    char* hb = smA + (buf * 2 + 0) * 16384 + r * 256;
    char* lb = smA + (buf * 2 + 1) * 16384 + r * 256;
    int sw = r & 7;
    #pragma unroll
    for (int cc = 0; cc < 4; cc++) {
        float xs[8] = {v[cc*2].x, v[cc*2].y, v[cc*2].z, v[cc*2].w,
                       v[cc*2+1].x, v[cc*2+1].y, v[cc*2+1].z, v[cc*2+1].w};
        uint32_t hw[4], lw[4];
        #pragma unroll
        for (int p = 0; p < 4; p++) {
            float x0 = xs[p*2], x1 = xs[p*2+1];
            float h0 = bfr(x0), h1 = bfr(x1);
            hw[p] = pbf2(x0, x1);
            lw[p] = pbf2(x0 - h0, x1 - h1);
        }
        int phys = (cq * 4 + cc) ^ sw;
        *(uint4*)(hb + phys * 16) = make_uint4(hw[0], hw[1], hw[2], hw[3]);
        *(uint4*)(lb + phys * 16) = make_uint4(lw[0], lw[1], lw[2], lw[3]);
    }
}

__global__ __launch_bounds__(256, 1)
void k_gemm_bf(const float* __restrict__ A, float* __restrict__ out,
               const float* __restrict__ bias,
               const float* __restrict__ attn_src,
               const float* __restrict__ attn_dst, int M) {
    extern __shared__ char sm[];
    uint32_t sb = smem_to_u32(sm);
    int tid = threadIdx.x, wid = tid >> 5, lane = tid & 31;
    int warp_m = wid & 1, warp_n = wid >> 1;

    // copy B fragments (128 KB)
    {
        const uint4* g = (const uint4*)d_Bf;
        uint4* s = (uint4*)sm;
        #pragma unroll
        for (int j = 0; j < 32; j++) s[j * 256 + tid] = g[j * 256 + tid];
    }
    int t0 = blockIdx.x * 2;
    fillA(A, t0 * 64, 0, sm + SMEM_A_OFF, tid, M);
    __syncthreads();
    bool has2 = (t0 + 1) < NT_TILES;
    if (has2) fillA(A, (t0 + 1) * 64, 1, sm + SMEM_A_OFF, tid, M);

    const uint2* B2 = (const uint2*)sm;
    int rl = lane & 15, cl = lane >> 4;
    int lr = lane >> 2, lc = (lane & 3) * 2;

    for (int ti = 0; ti < 2; ti++) {
        if (ti == 1 && !has2) break;
        int row0 = (t0 + ti) * 64;

        float acc[2][8][4];
        #pragma unroll
        for (int a = 0; a < 2; a++)
            #pragma unroll
            for (int b = 0; b < 8; b++)
                #pragma unroll
                for (int q = 0; q < 4; q++) acc[a][b][q] = 0.f;

        uint32_t aH = sb + SMEM_A_OFF + (ti * 2) * 16384;
        uint32_t aL = aH + 16384;

        #pragma unroll
        for (int kt = 0; kt < 8; kt++) {
            uint32_t ah[2][4], al[2][4];
            #pragma unroll
            for (int mt = 0; mt < 2; mt++) {
                int r = warp_m * 32 + mt * 16 + rl;
                int c = kt * 2 + cl;
                uint32_t off = (uint32_t)(r * 256 + ((c ^ (r & 7)) << 4));
                ldsm4(ah[mt], aH + off);
                ldsm4(al[mt], aL + off);
            }
            #pragma unroll
            for (int nt = 0; nt < 8; nt++) {
                int bi = (kt * 32 + warp_n * 8 + nt) * 32 + lane;
                uint2 bh = B2[bi];
                uint2 bl = B2[bi + 8192];
                #pragma unroll
                for (int mt = 0; mt < 2; mt++) {
                    mma_bf16(acc[mt][nt], ah[mt], bh.x, bh.y);
                    mma_bf16(acc[mt][nt], al[mt], bh.x, bh.y);
                    mma_bf16(acc[mt][nt], ah[mt], bl.x, bl.y);
                }
            }
        }

        // ---- epilogue ----
        #pragma unroll
        for (int mt = 0; mt < 2; mt++) {
            int r0g = row0 + warp_m * 32 + mt * 16 + lr;
            #pragma unroll
            for (int nt = 0; nt < 8; nt++) {
                int col = warp_n * 64 + nt * 8 + lc;
                float* c = acc[mt][nt];
                if (col < 128) {
                    if (r0g < M)
                        *(float2*)(d_feat + (size_t)r0g * 128 + col) =
                            make_float2(c[0], c[1]);
                    if (r0g + 8 < M)
                        *(float2*)(d_feat + (size_t)(r0g + 8) * 128 + col) =
                            make_float2(c[2], c[3]);
                } else {
                    int oc = col - 128;
                    float2 bz = *(const float2*)(bias + oc);
                    if (r0g < M)
                        *(float2*)(out + (size_t)r0g * 128 + oc) =
                            make_float2(c[0] + bz.x, c[1] + bz.y);
                    if (r0g + 8 < M)
                        *(float2*)(out + (size_t)(r0g + 8) * 128 + oc) =
                            make_float2(c[2] + bz.x, c[3] + bz.y);
                }
            }
            // fused a_src / a_dst (feat warps only)
            if (warp_n < 2) {
                #pragma unroll
                for (int hl = 0; hl < 2; hl++) {
                    int head = warp_n * 2 + hl;
                    float ps0 = 0.f, ps1 = 0.f, pd0 = 0.f, pd1 = 0.f;
                    #pragma unroll
                    for (int ntl = 0; ntl < 4; ntl++) {
                        int nt = hl * 4 + ntl;
                        int cih = ntl * 8 + lc;
                        float s0 = __ldg(attn_src + head * 32 + cih);
                        float s1 = __ldg(attn_src + head * 32 + cih + 1);
                        float e0 = __ldg(attn_dst + head * 32 + cih);
                        float e1 = __ldg(attn_dst + head * 32 + cih + 1);
                        float* c = acc[mt][nt];
                        ps0 += c[0] * s0 + c[1] * s1;
                        ps1 += c[2] * s0 + c[3] * s1;
                        pd0 += c[0] * e0 + c[1] * e1;
                        pd1 += c[2] * e0 + c[3] * e1;
                    }
                    #pragma unroll
                    for (int o = 1; o < 4; o <<= 1) {
                        ps0 += __shfl_xor_sync(0xffffffffu, ps0, o);
                        ps1 += __shfl_xor_sync(0xffffffffu, ps1, o);
                        pd0 += __shfl_xor_sync(0xffffffffu, pd0, o);
                        pd1 += __shfl_xor_sync(0xffffffffu, pd1, o);
                    }
                    if ((lane & 3) == 0) {
                        if (r0g < M) {
                            d_asrc[r0g * 4 + head] = ps0;
                            d_adst[r0g * 4 + head] = pd0;
                        }
                        if (r0g + 8 < M) {
                            d_asrc[(r0g + 8) * 4 + head] = ps1;
                            d_adst[(r0g + 8) * 4 + head] = pd1;
                        }
                    }
                }
            }
        }
        if (ti == 0 && has2) __syncthreads();
    }
}

// ---------------- K3: histogram ----------------
__global__ void k_hist(const int* __restrict__ dst) {
    int i4 = (blockIdx.x * blockDim.x + threadIdx.x) * 4;
    if (i4 + 3 < N_EDGES) {
        int4 d = *(const int4*)(dst + i4);
        atomicAdd(&d_count[d.x], 1);
        atomicAdd(&d_count[d.y], 1);
        atomicAdd(&d_count[d.z], 1);
        atomicAdd(&d_count[d.w], 1);
    } else {
        for (int i = i4; i < N_EDGES; i++) atomicAdd(&d_count[dst[i]], 1);
    }
}

// ---------------- K4: single-block exclusive scan ----------------
__global__ void k_scan() {
    __shared__ int wsum[32];
    int tid = threadIdx.x;
    int lane = tid & 31, wid = tid >> 5;
    int running = 0;
    if (tid == 0) d_offsets[0] = 0;
    for (int b = 0; b < N_NODES; b += 4096) {
        int i0 = b + tid * 4;
        int v0 = 0, v1 = 0, v2 = 0, v3 = 0;
        if (i0 + 3 < N_NODES) {
            int4 v = *(const int4*)&d_count[i0];
            v0 = v.x; v1 = v.y; v2 = v.z; v3 = v.w;
        } else {
            if (i0 + 0 < N_NODES) v0 = d_count[i0 + 0];
            if (i0 + 1 < N_NODES) v1 = d_count[i0 + 1];
            if (i0 + 2 < N_NODES) v2 = d_count[i0 + 2];
            if (i0 + 3 < N_NODES) v3 = d_count[i0 + 3];
        }
        int p0 = v0, p1 = p0 + v1, p2 = p1 + v2, p3 = p2 + v3;
        int x = p3;
        #pragma unroll
        for (int o = 1; o < 32; o <<= 1) {
            int t = __shfl_up_sync(0xffffffffu, x, o);
            if (lane >= o) x += t;
        }
        if (lane == 31) wsum[wid] = x;
        __syncthreads();
        if (wid == 0) {
            int y = wsum[lane];
            #pragma unroll
            for (int o = 1; o < 32; o <<= 1) {
                int t = __shfl_up_sync(0xffffffffu, y, o);
                if (lane >= o) y += t;
            }
            wsum[lane] = y;
        }
        __syncthreads();
        int warpoff = (wid > 0) ? wsum[wid - 1] : 0;
        int bs = running + warpoff + (x - p3);
        if (i0 + 0 < N_NODES) d_offsets[i0 + 1] = bs + p0;
        if (i0 + 1 < N_NODES) d_offsets[i0 + 2] = bs + p1;
        if (i0 + 2 < N_NODES) d_offsets[i0 + 3] = bs + p2;
        if (i0 + 3 < N_NODES) d_offsets[i0 + 4] = bs + p3;
        int tot = wsum[31];
        __syncthreads();
        running += tot;
    }
}

// ---------------- K6: edge logits + inline CSR fill ----------------
__global__ void k_edge_e(const float* __restrict__ edge_inputs,
                         const int* __restrict__ src,
                         const int* __restrict__ dst) {
    __shared__ float sweh[64];
    if (threadIdx.x < 64) sweh[threadIdx.x] = d_weh[threadIdx.x];
    __syncthreads();

    int e = blockIdx.x * blockDim.x + threadIdx.x;
    if (e >= N_EDGES) return;

    int s = src[e];
    int d = dst[e];
    float4 as = *(const float4*)(d_asrc + s * 4);
    float4 ad = *(const float4*)(d_adst + d * 4);

    float ae[4] = {0.f, 0.f, 0.f, 0.f};
    const float* ep = edge_inputs + (size_t)e * 16;
    #pragma unroll
    for (int kq = 0; kq < 4; kq++) {
        float4 ev = *(const float4*)(ep + kq * 4);
        float efs[4] = {ev.x, ev.y, ev.z, ev.w};
        #pragma unroll
        for (int kk = 0; kk < 4; kk++) {
            int k = kq * 4 + kk;
            #pragma unroll
            for (int h = 0; h < 4; h++) ae[h] += efs[kk] * sweh[k * 4 + h];
        }
    }

    float av[4] = {as.x, as.y, as.z, as.w};
    float dv[4] = {ad.x, ad.y, ad.z, ad.w};
    float res[4];
    #pragma unroll
    for (int h = 0; h < 4; h++) {
        float v = av[h] + dv[h] + ae[h];
        res[h] = (v > 0.f) ? v : NEG_SLOPE * v;
    }

    int p = d_offsets[d] + atomicAdd(&d_count2[d], 1);
    d_pe[p] = make_float4(res[0], res[1], res[2], res[3]);
    d_ps[p] = s;
}

// ---------------- K7: warp-per-node single-pass softmax + aggregate --------
__global__ void k_aggregate(float* __restrict__ out) {
    int warp = (blockIdx.x * blockDim.x + threadIdx.x) >> 5;
    int lane = threadIdx.x & 31;
    if (warp >= N_NODES) return;
    int n = warp;

    int begin = d_offsets[n];
    int deg = d_offsets[n + 1] - begin;
    if (deg == 0) return;

    int hl = lane >> 3;
    float s0 = 0.f, s1 = 0.f, s2 = 0.f, s3 = 0.f;
    float acc0 = 0.f, acc1 = 0.f, acc2 = 0.f, acc3 = 0.f;

    for (int b = 0; b < deg; b += 32) {
        int j = b + lane;
        float4 w4 = make_float4(0.f, 0.f, 0.f, 0.f);
        int sn = 0;
        if (j < deg) {
            float4 ev = d_pe[begin + j];
            sn = d_ps[begin + j];
            w4.x = __expf(ev.x);
            w4.y = __expf(ev.y);
            w4.z = __expf(ev.z);
            w4.w = __expf(ev.w);
        }
        s0 += w4.x; s1 += w4.y; s2 += w4.z; s3 += w4.w;
        int cnt = min(32, deg - b);
        #pragma unroll 4
        for (int k = 0; k < cnt; k++) {
            float wx = __shfl_sync(0xffffffffu, w4.x, k);
            float wy = __shfl_sync(0xffffffffu, w4.y, k);
            float wz = __shfl_sync(0xffffffffu, w4.z, k);
            float ww = __shfl_sync(0xffffffffu, w4.w, k);
            int snk = __shfl_sync(0xffffffffu, sn, k);
            float w = (hl < 2) ? (hl == 0 ? wx : wy) : (hl == 2 ? wz : ww);
            float4 fv = *(const float4*)(d_feat + (size_t)snk * 128 + lane * 4);
            acc0 += fv.x * w;
            acc1 += fv.y * w;
            acc2 += fv.z * w;
            acc3 += fv.w * w;
        }
    }
    #pragma unroll
    for (int o = 16; o > 0; o >>= 1) {
        s0 += __shfl_xor_sync(0xffffffffu, s0, o);
        s1 += __shfl_xor_sync(0xffffffffu, s1, o);
        s2 += __shfl_xor_sync(0xffffffffu, s2, o);
        s3 += __shfl_xor_sync(0xffffffffu, s3, o);
    }
    float s = (hl < 2) ? (hl == 0 ? s0 : s1) : (hl == 2 ? s2 : s3);
    float inv = 1.f / s;

    float4* op = (float4*)(out + (size_t)n * 128 + lane * 4);
    float4 ov = *op;  // residual + bias from GEMM epilogue
    ov.x += acc0 * inv; ov.y += acc1 * inv;
    ov.z += acc2 * inv; ov.w += acc3 * inv;
    *op = ov;
}

// ---------------------------------------------------------------------------
extern "C" void kernel_launch(void* const* d_in, const int* in_sizes, int n_in,
                              void* d_out, int out_size) {
    const float* node_inputs = (const float*)d_in[0];
    const float* edge_inputs = (const float*)d_in[1];
    const int*   src         = (const int*)d_in[2];
    const int*   dst         = (const int*)d_in[3];
    const float* W_fc        = (const float*)d_in[4];
    const float* attn_src_p  = (const float*)d_in[5];
    const float* attn_dst_p  = (const float*)d_in[6];
    const float* W_edge      = (const float*)d_in[7];
    const float* attn_edge_p = (const float*)d_in[8];
    const float* W_res       = (const float*)d_in[9];
    const float* bias_p      = (const float*)d_in[10];
    float* out = (float*)d_out;

    cudaFuncSetAttribute(k_gemm_bf, cudaFuncAttributeMaxDynamicSharedMemorySize,
                         GEMM_SMEM);

    k_init<<<256, 256>>>();
    k_weh<<<1, 64>>>(W_edge, attn_edge_p);
    k_bsplit<<<64, 256>>>(W_fc, W_res);
    k_gemm_bf<<<(NT_TILES + 1) / 2, 256, GEMM_SMEM>>>(
        node_inputs, out, bias_p, attn_src_p, attn_dst_p, N_NODES);
    k_hist<<<(N_EDGES / 4 + 255) / 256, 256>>>(dst);
    k_scan<<<1, 1024>>>();
    k_edge_e<<<(N_EDGES + 255) / 256, 256>>>(edge_inputs, src, dst);
    k_aggregate<<<(N_NODES * 32 + 255) / 256, 256>>>(out);
}

// round 6
// speedup vs baseline: 1.5951x; 1.1329x over previous
#include <cuda_runtime.h>
#include <cuda_fp16.h>
#include <cuda_bf16.h>
#include <cstdint>

// ---------------------------------------------------------------------------
// GATConv GB300 (sm_103): N=100000, E=1600000, H=4, D=32
//   K0   zero counters
//   K0b  w_eh[k][h]
//   K0c  B fragments (bf16 hi/lo) of [W_fc|W_res], mma-fragment-major
//   K1   PERSISTENT mma.sync bf16 GEMM (3-term split AhBh+AlBh+AhBl):
//        feat(fp16) / out(+bias); a_src/a_dst fused in epilogue
//   K3   histogram count[dst]
//   K4   exclusive scan -> offsets
//   K6   edge logits + inline CSR fill -> {e4},{src} in CSR order
//   K7   warp-per-node single-pass softmax + fp16 gather-aggregate
// ---------------------------------------------------------------------------

#define N_NODES 100000
#define N_EDGES 1600000
#define NEG_SLOPE 0.2f
#define NT_TILES ((N_NODES + 63) / 64)
#define GEMM_GRID 148

__device__ __align__(16) __half d_feat_h[N_NODES * 128];
__device__ __align__(16) float  d_asrc[N_NODES * 4];
__device__ __align__(16) float  d_adst[N_NODES * 4];
__device__ __align__(16) float4 d_pe[N_EDGES];
__device__ __align__(16) int    d_ps[N_EDGES];
__device__ __align__(16) float  d_weh[64];        // [k=16][h=4]
__device__ __align__(16) uint2  d_Bf[16384];      // [term][kt8][ntg32][lane32]
__device__ __align__(16) int    d_count[N_NODES + 4];
__device__ __align__(16) int    d_count2[N_NODES];
__device__ __align__(16) int    d_offsets[N_NODES + 1];

// ---------------- helpers ----------------
__device__ __forceinline__ uint32_t smem_to_u32(const void* p) {
    uint32_t a;
    asm("{ .reg .u64 t; cvta.to.shared.u64 t, %1; cvt.u32.u64 %0, t; }"
        : "=r"(a) : "l"(p));
    return a;
}
__device__ __forceinline__ float bfr(float x) {
    return __bfloat162float(__float2bfloat16(x));
}
__device__ __forceinline__ uint32_t pbf2(float a, float b) {
    uint16_t ua = __bfloat16_as_ushort(__float2bfloat16(a));
    uint16_t ub = __bfloat16_as_ushort(__float2bfloat16(b));
    return (uint32_t)ua | ((uint32_t)ub << 16);
}
__device__ __forceinline__ void ldsm4(uint32_t* a, uint32_t addr) {
    asm volatile("ldmatrix.sync.aligned.m8n8.x4.shared.b16 {%0,%1,%2,%3}, [%4];"
        : "=r"(a[0]), "=r"(a[1]), "=r"(a[2]), "=r"(a[3]) : "r"(addr));
}
__device__ __forceinline__ void mma_bf16(float* c, const uint32_t* a,
                                         uint32_t b0, uint32_t b1) {
    asm volatile(
        "mma.sync.aligned.m16n8k16.row.col.f32.bf16.bf16.f32 "
        "{%0,%1,%2,%3}, {%4,%5,%6,%7}, {%8,%9}, {%0,%1,%2,%3};"
        : "+f"(c[0]), "+f"(c[1]), "+f"(c[2]), "+f"(c[3])
        : "r"(a[0]), "r"(a[1]), "r"(a[2]), "r"(a[3]), "r"(b0), "r"(b1));
}

// ---------------- K0: zero counters ----------------
__global__ void k_init() {
    int i = blockIdx.x * blockDim.x + threadIdx.x;
    int total = (N_NODES + 4) + N_NODES;
    for (; i < total; i += gridDim.x * blockDim.x) {
        if (i < N_NODES + 4) d_count[i] = 0;
        else d_count2[i - (N_NODES + 4)] = 0;
    }
}

// ---------------- K0b: w_eh ----------------
__global__ void k_weh(const float* __restrict__ W_edge,
                      const float* __restrict__ attn_edge) {
    int t = threadIdx.x;
    if (t >= 64) return;
    int k = t >> 2, h = t & 3;
    float s = 0.f;
    #pragma unroll
    for (int d = 0; d < 32; d++)
        s += W_edge[k * 128 + h * 32 + d] * attn_edge[h * 32 + d];
    d_weh[k * 4 + h] = s;
}

// ---------------- K0c: B fragments hi/lo ----------------
__global__ void k_bsplit(const float* __restrict__ W_fc,
                         const float* __restrict__ W_res) {
    int i = blockIdx.x * blockDim.x + threadIdx.x;
    if (i >= 16384) return;
    int lane = i & 31, ntg = (i >> 5) & 31, kt = (i >> 10) & 7, term = i >> 13;
    int n = ntg * 8 + (lane >> 2);
    int kb = kt * 16 + (lane & 3) * 2;
    float w[4];
    #pragma unroll
    for (int j = 0; j < 4; j++) {
        int k = kb + (j >> 1) * 8 + (j & 1);
        w[j] = (n < 128) ? W_fc[k * 128 + n] : W_res[k * 128 + n - 128];
    }
    uint32_t r0, r1;
    if (term == 0) {
        r0 = pbf2(w[0], w[1]);
        r1 = pbf2(w[2], w[3]);
    } else {
        r0 = pbf2(w[0] - bfr(w[0]), w[1] - bfr(w[1]));
        r1 = pbf2(w[2] - bfr(w[2]), w[3] - bfr(w[3]));
    }
    d_Bf[i] = make_uint2(r0, r1);
}

// ---------------- K1: persistent bf16x3 mma GEMM ----------------
// smem: [0,131072) B frags; [131072,196608) A: [buf][term][64r][16 x 16B]
#define SMEM_A_OFF 131072
#define GEMM_SMEM  196608

__global__ __launch_bounds__(256, 1)
void k_gemm_bf(const float* __restrict__ A, float* __restrict__ out,
               const float* __restrict__ bias,
               const float* __restrict__ attn_src,
               const float* __restrict__ attn_dst, int M) {
    extern __shared__ char sm[];
    uint32_t sb = smem_to_u32(sm);
    int tid = threadIdx.x, wid = tid >> 5, lane = tid & 31;
    int warp_m = wid & 1, warp_n = wid >> 1;

    // copy B fragments once (128 KB)
    {
        const uint4* g = (const uint4*)d_Bf;
        uint4* s = (uint4*)sm;
        #pragma unroll
        for (int j = 0; j < 32; j++) s[j * 256 + tid] = g[j * 256 + tid];
    }

    int r = tid >> 2, cq = tid & 3;        // A load/convert mapping
    float4 a_st[8];

    auto load_regs = [&](int tile) {
        int grow = tile * 64 + r;
        if (grow < M) {
            const float4* ap = (const float4*)(A + (size_t)grow * 128 + cq * 32);
            #pragma unroll
            for (int q = 0; q < 8; q++) a_st[q] = __ldg(ap + q);
        } else {
            #pragma unroll
            for (int q = 0; q < 8; q++) a_st[q] = make_float4(0.f, 0.f, 0.f, 0.f);
        }
    };
    auto store_stage = [&](int buf) {
        char* hb = sm + SMEM_A_OFF + (buf * 2 + 0) * 16384 + r * 256;
        char* lb = sm + SMEM_A_OFF + (buf * 2 + 1) * 16384 + r * 256;
        int sw = r & 7;
        #pragma unroll
        for (int cc = 0; cc < 4; cc++) {
            float xs[8] = {a_st[cc*2].x, a_st[cc*2].y, a_st[cc*2].z, a_st[cc*2].w,
                           a_st[cc*2+1].x, a_st[cc*2+1].y, a_st[cc*2+1].z, a_st[cc*2+1].w};
            uint32_t hw[4], lw[4];
            #pragma unroll
            for (int p = 0; p < 4; p++) {
                float x0 = xs[p*2], x1 = xs[p*2+1];
                float h0 = bfr(x0), h1 = bfr(x1);
                hw[p] = pbf2(x0, x1);
                lw[p] = pbf2(x0 - h0, x1 - h1);
            }
            int phys = (cq * 4 + cc) ^ sw;
            *(uint4*)(hb + phys * 16) = make_uint4(hw[0], hw[1], hw[2], hw[3]);
            *(uint4*)(lb + phys * 16) = make_uint4(lw[0], lw[1], lw[2], lw[3]);
        }
    };

    const uint2* B2 = (const uint2*)sm;
    int rl = lane & 15, cl = lane >> 4;
    int lr = lane >> 2, lc = (lane & 3) * 2;

    int tile = blockIdx.x;
    if (tile < NT_TILES) load_regs(tile);
    store_stage(0);
    __syncthreads();
    int buf = 0;

    for (; tile < NT_TILES; tile += GEMM_GRID) {
        int nxt = tile + GEMM_GRID;
        bool hn = nxt < NT_TILES;
        if (hn) load_regs(nxt);

        float acc[2][8][4];
        #pragma unroll
        for (int a = 0; a < 2; a++)
            #pragma unroll
            for (int b = 0; b < 8; b++)
                #pragma unroll
                for (int q = 0; q < 4; q++) acc[a][b][q] = 0.f;

        uint32_t aH = sb + SMEM_A_OFF + (buf * 2) * 16384;
        uint32_t aL = aH + 16384;

        #pragma unroll
        for (int kt = 0; kt < 8; kt++) {
            uint32_t ah[2][4], al[2][4];
            #pragma unroll
            for (int mt = 0; mt < 2; mt++) {
                int rr = warp_m * 32 + mt * 16 + rl;
                int c = kt * 2 + cl;
                uint32_t off = (uint32_t)(rr * 256 + ((c ^ (rr & 7)) << 4));
                ldsm4(ah[mt], aH + off);
                ldsm4(al[mt], aL + off);
            }
            #pragma unroll
            for (int nt = 0; nt < 8; nt++) {
                int bi = (kt * 32 + warp_n * 8 + nt) * 32 + lane;
                uint2 bh = B2[bi];
                uint2 bl = B2[bi + 8192];
                #pragma unroll
                for (int mt = 0; mt < 2; mt++) {
                    mma_bf16(acc[mt][nt], ah[mt], bh.x, bh.y);
                    mma_bf16(acc[mt][nt], al[mt], bh.x, bh.y);
                    mma_bf16(acc[mt][nt], ah[mt], bl.x, bl.y);
                }
            }
        }

        if (hn) store_stage(buf ^ 1);

        // ---- epilogue ----
        int row0 = tile * 64;
        #pragma unroll
        for (int mt = 0; mt < 2; mt++) {
            int r0g = row0 + warp_m * 32 + mt * 16 + lr;
            #pragma unroll
            for (int nt = 0; nt < 8; nt++) {
                int col = warp_n * 64 + nt * 8 + lc;
                float* c = acc[mt][nt];
                if (col < 128) {
                    if (r0g < M)
                        *(__half2*)(d_feat_h + (size_t)r0g * 128 + col) =
                            __floats2half2_rn(c[0], c[1]);
                    if (r0g + 8 < M)
                        *(__half2*)(d_feat_h + (size_t)(r0g + 8) * 128 + col) =
                            __floats2half2_rn(c[2], c[3]);
                } else {
                    int oc = col - 128;
                    float2 bz = *(const float2*)(bias + oc);
                    if (r0g < M)
                        *(float2*)(out + (size_t)r0g * 128 + oc) =
                            make_float2(c[0] + bz.x, c[1] + bz.y);
                    if (r0g + 8 < M)
                        *(float2*)(out + (size_t)(r0g + 8) * 128 + oc) =
                            make_float2(c[2] + bz.x, c[3] + bz.y);
                }
            }
            if (warp_n < 2) {
                #pragma unroll
                for (int hl = 0; hl < 2; hl++) {
                    int head = warp_n * 2 + hl;
                    float ps0 = 0.f, ps1 = 0.f, pd0 = 0.f, pd1 = 0.f;
                    #pragma unroll
                    for (int ntl = 0; ntl < 4; ntl++) {
                        int nt = hl * 4 + ntl;
                        int cih = ntl * 8 + lc;
                        float s0 = __ldg(attn_src + head * 32 + cih);
                        float s1 = __ldg(attn_src + head * 32 + cih + 1);
                        float e0 = __ldg(attn_dst + head * 32 + cih);
                        float e1 = __ldg(attn_dst + head * 32 + cih + 1);
                        float* c = acc[mt][nt];
                        ps0 += c[0] * s0 + c[1] * s1;
                        ps1 += c[2] * s0 + c[3] * s1;
                        pd0 += c[0] * e0 + c[1] * e1;
                        pd1 += c[2] * e0 + c[3] * e1;
                    }
                    #pragma unroll
                    for (int o = 1; o < 4; o <<= 1) {
                        ps0 += __shfl_xor_sync(0xffffffffu, ps0, o);
                        ps1 += __shfl_xor_sync(0xffffffffu, ps1, o);
                        pd0 += __shfl_xor_sync(0xffffffffu, pd0, o);
                        pd1 += __shfl_xor_sync(0xffffffffu, pd1, o);
                    }
                    if ((lane & 3) == 0) {
                        if (r0g < M) {
                            d_asrc[r0g * 4 + head] = ps0;
                            d_adst[r0g * 4 + head] = pd0;
                        }
                        if (r0g + 8 < M) {
                            d_asrc[(r0g + 8) * 4 + head] = ps1;
                            d_adst[(r0g + 8) * 4 + head] = pd1;
                        }
                    }
                }
            }
        }
        __syncthreads();
        buf ^= 1;
    }
}

// ---------------- K3: histogram ----------------
__global__ void k_hist(const int* __restrict__ dst) {
    int i4 = (blockIdx.x * blockDim.x + threadIdx.x) * 4;
    if (i4 + 3 < N_EDGES) {
        int4 d = *(const int4*)(dst + i4);
        atomicAdd(&d_count[d.x], 1);
        atomicAdd(&d_count[d.y], 1);
        atomicAdd(&d_count[d.z], 1);
        atomicAdd(&d_count[d.w], 1);
    } else {
        for (int i = i4; i < N_EDGES; i++) atomicAdd(&d_count[dst[i]], 1);
    }
}

// ---------------- K4: single-block exclusive scan ----------------
__global__ void k_scan() {
    __shared__ int wsum[32];
    int tid = threadIdx.x;
    int lane = tid & 31, wid = tid >> 5;
    int running = 0;
    if (tid == 0) d_offsets[0] = 0;
    for (int b = 0; b < N_NODES; b += 4096) {
        int i0 = b + tid * 4;
        int v0 = 0, v1 = 0, v2 = 0, v3 = 0;
        if (i0 + 3 < N_NODES) {
            int4 v = *(const int4*)&d_count[i0];
            v0 = v.x; v1 = v.y; v2 = v.z; v3 = v.w;
        } else {
            if (i0 + 0 < N_NODES) v0 = d_count[i0 + 0];
            if (i0 + 1 < N_NODES) v1 = d_count[i0 + 1];
            if (i0 + 2 < N_NODES) v2 = d_count[i0 + 2];
            if (i0 + 3 < N_NODES) v3 = d_count[i0 + 3];
        }
        int p0 = v0, p1 = p0 + v1, p2 = p1 + v2, p3 = p2 + v3;
        int x = p3;
        #pragma unroll
        for (int o = 1; o < 32; o <<= 1) {
            int t = __shfl_up_sync(0xffffffffu, x, o);
            if (lane >= o) x += t;
        }
        if (lane == 31) wsum[wid] = x;
        __syncthreads();
        if (wid == 0) {
            int y = wsum[lane];
            #pragma unroll
            for (int o = 1; o < 32; o <<= 1) {
                int t = __shfl_up_sync(0xffffffffu, y, o);
                if (lane >= o) y += t;
            }
            wsum[lane] = y;
        }
        __syncthreads();
        int warpoff = (wid > 0) ? wsum[wid - 1] : 0;
        int bs = running + warpoff + (x - p3);
        if (i0 + 0 < N_NODES) d_offsets[i0 + 1] = bs + p0;
        if (i0 + 1 < N_NODES) d_offsets[i0 + 2] = bs + p1;
        if (i0 + 2 < N_NODES) d_offsets[i0 + 3] = bs + p2;
        if (i0 + 3 < N_NODES) d_offsets[i0 + 4] = bs + p3;
        int tot = wsum[31];
        __syncthreads();
        running += tot;
    }
}

// ---------------- K6: edge logits + inline CSR fill ----------------
__global__ void k_edge_e(const float* __restrict__ edge_inputs,
                         const int* __restrict__ src,
                         const int* __restrict__ dst) {
    __shared__ float sweh[64];
    if (threadIdx.x < 64) sweh[threadIdx.x] = d_weh[threadIdx.x];
    __syncthreads();

    int e = blockIdx.x * blockDim.x + threadIdx.x;
    if (e >= N_EDGES) return;

    int s = src[e];
    int d = dst[e];
    float4 as = *(const float4*)(d_asrc + s * 4);
    float4 ad = *(const float4*)(d_adst + d * 4);

    float ae[4] = {0.f, 0.f, 0.f, 0.f};
    const float* ep = edge_inputs + (size_t)e * 16;
    #pragma unroll
    for (int kq = 0; kq < 4; kq++) {
        float4 ev = *(const float4*)(ep + kq * 4);
        float efs[4] = {ev.x, ev.y, ev.z, ev.w};
        #pragma unroll
        for (int kk = 0; kk < 4; kk++) {
            int k = kq * 4 + kk;
            #pragma unroll
            for (int h = 0; h < 4; h++) ae[h] += efs[kk] * sweh[k * 4 + h];
        }
    }

    float av[4] = {as.x, as.y, as.z, as.w};
    float dv[4] = {ad.x, ad.y, ad.z, ad.w};
    float res[4];
    #pragma unroll
    for (int h = 0; h < 4; h++) {
        float v = av[h] + dv[h] + ae[h];
        res[h] = (v > 0.f) ? v : NEG_SLOPE * v;
    }

    int p = d_offsets[d] + atomicAdd(&d_count2[d], 1);
    d_pe[p] = make_float4(res[0], res[1], res[2], res[3]);
    d_ps[p] = s;
}

// ---------------- K7: warp-per-node single-pass softmax + aggregate --------
__global__ void k_aggregate(float* __restrict__ out) {
    int warp = (blockIdx.x * blockDim.x + threadIdx.x) >> 5;
    int lane = threadIdx.x & 31;
    if (warp >= N_NODES) return;
    int n = warp;

    int begin = d_offsets[n];
    int deg = d_offsets[n + 1] - begin;
    if (deg == 0) return;

    int hl = lane >> 3;
    float s0 = 0.f, s1 = 0.f, s2 = 0.f, s3 = 0.f;
    float acc0 = 0.f, acc1 = 0.f, acc2 = 0.f, acc3 = 0.f;

    for (int b = 0; b < deg; b += 32) {
        int j = b + lane;
        float4 w4 = make_float4(0.f, 0.f, 0.f, 0.f);
        int sn = 0;
        if (j < deg) {
            float4 ev = d_pe[begin + j];
            sn = d_ps[begin + j];
            w4.x = __expf(ev.x);
            w4.y = __expf(ev.y);
            w4.z = __expf(ev.z);
            w4.w = __expf(ev.w);
        }
        s0 += w4.x; s1 += w4.y; s2 += w4.z; s3 += w4.w;
        int cnt = min(32, deg - b);
        #pragma unroll 4
        for (int k = 0; k < cnt; k++) {
            float wx = __shfl_sync(0xffffffffu, w4.x, k);
            float wy = __shfl_sync(0xffffffffu, w4.y, k);
            float wz = __shfl_sync(0xffffffffu, w4.z, k);
            float ww = __shfl_sync(0xffffffffu, w4.w, k);
            int snk = __shfl_sync(0xffffffffu, sn, k);
            float w = (hl < 2) ? (hl == 0 ? wx : wy) : (hl == 2 ? wz : ww);
            const __half2* fp =
                (const __half2*)(d_feat_h + (size_t)snk * 128 + lane * 4);
            __half2 h0 = fp[0], h1 = fp[1];
            float2 f0 = __half22float2(h0);
            float2 f1 = __half22float2(h1);
            acc0 += f0.x * w;
            acc1 += f0.y * w;
            acc2 += f1.x * w;
            acc3 += f1.y * w;
        }
    }
    #pragma unroll
    for (int o = 16; o > 0; o >>= 1) {
        s0 += __shfl_xor_sync(0xffffffffu, s0, o);
        s1 += __shfl_xor_sync(0xffffffffu, s1, o);
        s2 += __shfl_xor_sync(0xffffffffu, s2, o);
        s3 += __shfl_xor_sync(0xffffffffu, s3, o);
    }
    float s = (hl < 2) ? (hl == 0 ? s0 : s1) : (hl == 2 ? s2 : s3);
    float inv = 1.f / s;

    float4* op = (float4*)(out + (size_t)n * 128 + lane * 4);
    float4 ov = *op;  // residual + bias from GEMM epilogue
    ov.x += acc0 * inv; ov.y += acc1 * inv;
    ov.z += acc2 * inv; ov.w += acc3 * inv;
    *op = ov;
}

// ---------------------------------------------------------------------------
extern "C" void kernel_launch(void* const* d_in, const int* in_sizes, int n_in,
                              void* d_out, int out_size) {
    const float* node_inputs = (const float*)d_in[0];
    const float* edge_inputs = (const float*)d_in[1];
    const int*   src         = (const int*)d_in[2];
    const int*   dst         = (const int*)d_in[3];
    const float* W_fc        = (const float*)d_in[4];
    const float* attn_src_p  = (const float*)d_in[5];
    const float* attn_dst_p  = (const float*)d_in[6];
    const float* W_edge      = (const float*)d_in[7];
    const float* attn_edge_p = (const float*)d_in[8];
    const float* W_res       = (const float*)d_in[9];
    const float* bias_p      = (const float*)d_in[10];
    float* out = (float*)d_out;

    cudaFuncSetAttribute(k_gemm_bf, cudaFuncAttributeMaxDynamicSharedMemorySize,
                         GEMM_SMEM);

    k_init<<<256, 256>>>();
    k_weh<<<1, 64>>>(W_edge, attn_edge_p);
    k_bsplit<<<64, 256>>>(W_fc, W_res);
    k_gemm_bf<<<GEMM_GRID, 256, GEMM_SMEM>>>(
        node_inputs, out, bias_p, attn_src_p, attn_dst_p, N_NODES);
    k_hist<<<(N_EDGES / 4 + 255) / 256, 256>>>(dst);
    k_scan<<<1, 1024>>>();
    k_edge_e<<<(N_EDGES + 255) / 256, 256>>>(edge_inputs, src, dst);
    k_aggregate<<<(N_NODES * 32 + 255) / 256, 256>>>(out);
}

// round 7
// speedup vs baseline: 1.7000x; 1.0658x over previous
#include <cuda_runtime.h>
#include <cuda_fp16.h>
#include <cuda_bf16.h>
#include <cstdint>

// ---------------------------------------------------------------------------
// GATConv GB300 (sm_103): N=100000, E=1600000, H=4, D=32
//   K0   zero counters
//   K0b  w_eh[k][h]
//   K0c  B fragments (bf16 hi/lo), mma-fragment-major
//   K1   PERSISTENT 512-thread mma.sync bf16 GEMM (3-term split):
//        feat(fp16) / out(+bias); a_src/a_dst fused in epilogue
//   K3   histogram count[dst]
//   K4   exclusive scan -> offsets
//   K6   edge logits + inline CSR fill -> {e4},{src} in CSR order
//   K7   warp-per-node single-pass softmax + fp16 gather-aggregate
// ---------------------------------------------------------------------------

#define N_NODES 100000
#define N_EDGES 1600000
#define NEG_SLOPE 0.2f
#define NT_TILES ((N_NODES + 63) / 64)
#define GEMM_GRID 148

__device__ __align__(16) __half d_feat_h[N_NODES * 128];
__device__ __align__(16) float  d_asrc[N_NODES * 4];
__device__ __align__(16) float  d_adst[N_NODES * 4];
__device__ __align__(16) float4 d_pe[N_EDGES];
__device__ __align__(16) int    d_ps[N_EDGES];
__device__ __align__(16) float  d_weh[64];        // [k=16][h=4]
__device__ __align__(16) uint2  d_Bf[16384];      // [term][kt8][ntg32][lane32]
__device__ __align__(16) int    d_count[N_NODES + 4];
__device__ __align__(16) int    d_count2[N_NODES];
__device__ __align__(16) int    d_offsets[N_NODES + 1];

// ---------------- helpers ----------------
__device__ __forceinline__ uint32_t smem_to_u32(const void* p) {
    uint32_t a;
    asm("{ .reg .u64 t; cvta.to.shared.u64 t, %1; cvt.u32.u64 %0, t; }"
        : "=r"(a) : "l"(p));
    return a;
}
__device__ __forceinline__ float bfr(float x) {
    return __bfloat162float(__float2bfloat16(x));
}
__device__ __forceinline__ uint32_t pbf2(float a, float b) {
    uint16_t ua = __bfloat16_as_ushort(__float2bfloat16(a));
    uint16_t ub = __bfloat16_as_ushort(__float2bfloat16(b));
    return (uint32_t)ua | ((uint32_t)ub << 16);
}
__device__ __forceinline__ void ldsm4(uint32_t* a, uint32_t addr) {
    asm volatile("ldmatrix.sync.aligned.m8n8.x4.shared.b16 {%0,%1,%2,%3}, [%4];"
        : "=r"(a[0]), "=r"(a[1]), "=r"(a[2]), "=r"(a[3]) : "r"(addr));
}
__device__ __forceinline__ void mma_bf16(float* c, const uint32_t* a,
                                         uint32_t b0, uint32_t b1) {
    asm volatile(
        "mma.sync.aligned.m16n8k16.row.col.f32.bf16.bf16.f32 "
        "{%0,%1,%2,%3}, {%4,%5,%6,%7}, {%8,%9}, {%0,%1,%2,%3};"
        : "+f"(c[0]), "+f"(c[1]), "+f"(c[2]), "+f"(c[3])
        : "r"(a[0]), "r"(a[1]), "r"(a[2]), "r"(a[3]), "r"(b0), "r"(b1));
}

// ---------------- K0: zero counters ----------------
__global__ void k_init() {
    int i = blockIdx.x * blockDim.x + threadIdx.x;
    int total = (N_NODES + 4) + N_NODES;
    for (; i < total; i += gridDim.x * blockDim.x) {
        if (i < N_NODES + 4) d_count[i] = 0;
        else d_count2[i - (N_NODES + 4)] = 0;
    }
}

// ---------------- K0b: w_eh ----------------
__global__ void k_weh(const float* __restrict__ W_edge,
                      const float* __restrict__ attn_edge) {
    int t = threadIdx.x;
    if (t >= 64) return;
    int k = t >> 2, h = t & 3;
    float s = 0.f;
    #pragma unroll
    for (int d = 0; d < 32; d++)
        s += W_edge[k * 128 + h * 32 + d] * attn_edge[h * 32 + d];
    d_weh[k * 4 + h] = s;
}

// ---------------- K0c: B fragments hi/lo ----------------
__global__ void k_bsplit(const float* __restrict__ W_fc,
                         const float* __restrict__ W_res) {
    int i = blockIdx.x * blockDim.x + threadIdx.x;
    if (i >= 16384) return;
    int lane = i & 31, ntg = (i >> 5) & 31, kt = (i >> 10) & 7, term = i >> 13;
    int n = ntg * 8 + (lane >> 2);
    int kb = kt * 16 + (lane & 3) * 2;
    float w[4];
    #pragma unroll
    for (int j = 0; j < 4; j++) {
        int k = kb + (j >> 1) * 8 + (j & 1);
        w[j] = (n < 128) ? W_fc[k * 128 + n] : W_res[k * 128 + n - 128];
    }
    uint32_t r0, r1;
    if (term == 0) {
        r0 = pbf2(w[0], w[1]);
        r1 = pbf2(w[2], w[3]);
    } else {
        r0 = pbf2(w[0] - bfr(w[0]), w[1] - bfr(w[1]));
        r1 = pbf2(w[2] - bfr(w[2]), w[3] - bfr(w[3]));
    }
    d_Bf[i] = make_uint2(r0, r1);
}

// ---------------- K1: persistent 512-thread bf16x3 mma GEMM ----------------
// smem: [0,131072) B frags; [131072,196608) A: [buf][term][64r][16 x 16B]
#define SMEM_A_OFF 131072
#define GEMM_SMEM  196608

__global__ __launch_bounds__(512, 1)
void k_gemm_bf(const float* __restrict__ A, float* __restrict__ out,
               const float* __restrict__ bias,
               const float* __restrict__ attn_src,
               const float* __restrict__ attn_dst, int M) {
    extern __shared__ char sm[];
    uint32_t sb = smem_to_u32(sm);
    int tid = threadIdx.x, wid = tid >> 5, lane = tid & 31;
    int warp_m = wid & 1, warp_n = wid >> 1;   // warp_n 0..7

    // copy B fragments once (128 KB)
    {
        const uint4* g = (const uint4*)d_Bf;
        uint4* s = (uint4*)sm;
        #pragma unroll
        for (int j = 0; j < 16; j++) s[j * 512 + tid] = g[j * 512 + tid];
    }

    int r = tid >> 3, cq = tid & 7;        // A fill: 16 floats per thread
    float4 a_st[4];

    auto load_regs = [&](int tile) {
        int grow = tile * 64 + r;
        if (grow < M) {
            const float4* ap = (const float4*)(A + (size_t)grow * 128 + cq * 16);
            #pragma unroll
            for (int q = 0; q < 4; q++) a_st[q] = __ldg(ap + q);
        } else {
            #pragma unroll
            for (int q = 0; q < 4; q++) a_st[q] = make_float4(0.f, 0.f, 0.f, 0.f);
        }
    };
    auto store_stage = [&](int buf) {
        char* hb = sm + SMEM_A_OFF + (buf * 2 + 0) * 16384 + r * 256;
        char* lb = sm + SMEM_A_OFF + (buf * 2 + 1) * 16384 + r * 256;
        int sw = r & 7;
        #pragma unroll
        for (int cc = 0; cc < 2; cc++) {
            float xs[8] = {a_st[cc*2].x, a_st[cc*2].y, a_st[cc*2].z, a_st[cc*2].w,
                           a_st[cc*2+1].x, a_st[cc*2+1].y, a_st[cc*2+1].z, a_st[cc*2+1].w};
            uint32_t hw[4], lw[4];
            #pragma unroll
            for (int p = 0; p < 4; p++) {
                float x0 = xs[p*2], x1 = xs[p*2+1];
                float h0 = bfr(x0), h1 = bfr(x1);
                hw[p] = pbf2(x0, x1);
                lw[p] = pbf2(x0 - h0, x1 - h1);
            }
            int phys = (cq * 2 + cc) ^ sw;
            *(uint4*)(hb + phys * 16) = make_uint4(hw[0], hw[1], hw[2], hw[3]);
            *(uint4*)(lb + phys * 16) = make_uint4(lw[0], lw[1], lw[2], lw[3]);
        }
    };

    const uint2* B2 = (const uint2*)sm;
    int rl = lane & 15, cl = lane >> 4;
    int lr = lane >> 2, lc = (lane & 3) * 2;

    int tile = blockIdx.x;
    if (tile < NT_TILES) load_regs(tile);
    store_stage(0);
    __syncthreads();
    int buf = 0;

    for (; tile < NT_TILES; tile += GEMM_GRID) {
        int nxt = tile + GEMM_GRID;
        bool hn = nxt < NT_TILES;
        if (hn) load_regs(nxt);

        float acc[2][4][4];
        #pragma unroll
        for (int a = 0; a < 2; a++)
            #pragma unroll
            for (int b = 0; b < 4; b++)
                #pragma unroll
                for (int q = 0; q < 4; q++) acc[a][b][q] = 0.f;

        uint32_t aH = sb + SMEM_A_OFF + (buf * 2) * 16384;
        uint32_t aL = aH + 16384;

        #pragma unroll
        for (int kt = 0; kt < 8; kt++) {
            uint32_t ah[2][4], al[2][4];
            #pragma unroll
            for (int mt = 0; mt < 2; mt++) {
                int rr = warp_m * 32 + mt * 16 + rl;
                int c = kt * 2 + cl;
                uint32_t off = (uint32_t)(rr * 256 + ((c ^ (rr & 7)) << 4));
                ldsm4(ah[mt], aH + off);
                ldsm4(al[mt], aL + off);
            }
            #pragma unroll
            for (int nt = 0; nt < 4; nt++) {
                int bi = (kt * 32 + warp_n * 4 + nt) * 32 + lane;
                uint2 bh = B2[bi];
                uint2 bl = B2[bi + 8192];
                #pragma unroll
                for (int mt = 0; mt < 2; mt++) {
                    mma_bf16(acc[mt][nt], ah[mt], bh.x, bh.y);
                    mma_bf16(acc[mt][nt], al[mt], bh.x, bh.y);
                    mma_bf16(acc[mt][nt], ah[mt], bl.x, bl.y);
                }
            }
        }

        if (hn) store_stage(buf ^ 1);

        // ---- epilogue: warp covers rows warp_m*32..+32, cols warp_n*32..+32
        int row0 = tile * 64;
        bool is_feat = (warp_n < 4);
        #pragma unroll
        for (int mt = 0; mt < 2; mt++) {
            int r0g = row0 + warp_m * 32 + mt * 16 + lr;
            #pragma unroll
            for (int nt = 0; nt < 4; nt++) {
                int col = warp_n * 32 + nt * 8 + lc;
                float* c = acc[mt][nt];
                if (is_feat) {
                    if (r0g < M)
                        *(__half2*)(d_feat_h + (size_t)r0g * 128 + col) =
                            __floats2half2_rn(c[0], c[1]);
                    if (r0g + 8 < M)
                        *(__half2*)(d_feat_h + (size_t)(r0g + 8) * 128 + col) =
                            __floats2half2_rn(c[2], c[3]);
                } else {
                    int oc = col - 128;
                    float2 bz = *(const float2*)(bias + oc);
                    if (r0g < M)
                        *(float2*)(out + (size_t)r0g * 128 + oc) =
                            make_float2(c[0] + bz.x, c[1] + bz.y);
                    if (r0g + 8 < M)
                        *(float2*)(out + (size_t)(r0g + 8) * 128 + oc) =
                            make_float2(c[2] + bz.x, c[3] + bz.y);
                }
            }
            if (is_feat) {
                int head = warp_n;            // this warp's 32 cols = one head
                float ps0 = 0.f, ps1 = 0.f, pd0 = 0.f, pd1 = 0.f;
                #pragma unroll
                for (int nt = 0; nt < 4; nt++) {
                    int cih = nt * 8 + lc;
                    float s0 = __ldg(attn_src + head * 32 + cih);
                    float s1 = __ldg(attn_src + head * 32 + cih + 1);
                    float e0 = __ldg(attn_dst + head * 32 + cih);
                    float e1 = __ldg(attn_dst + head * 32 + cih + 1);
                    float* c = acc[mt][nt];
                    ps0 += c[0] * s0 + c[1] * s1;
                    ps1 += c[2] * s0 + c[3] * s1;
                    pd0 += c[0] * e0 + c[1] * e1;
                    pd1 += c[2] * e0 + c[3] * e1;
                }
                #pragma unroll
                for (int o = 1; o < 4; o <<= 1) {
                    ps0 += __shfl_xor_sync(0xffffffffu, ps0, o);
                    ps1 += __shfl_xor_sync(0xffffffffu, ps1, o);
                    pd0 += __shfl_xor_sync(0xffffffffu, pd0, o);
                    pd1 += __shfl_xor_sync(0xffffffffu, pd1, o);
                }
                if ((lane & 3) == 0) {
                    if (r0g < M) {
                        d_asrc[r0g * 4 + head] = ps0;
                        d_adst[r0g * 4 + head] = pd0;
                    }
                    if (r0g + 8 < M) {
                        d_asrc[(r0g + 8) * 4 + head] = ps1;
                        d_adst[(r0g + 8) * 4 + head] = pd1;
                    }
                }
            }
        }
        __syncthreads();
        buf ^= 1;
    }
}

// ---------------- K3: histogram ----------------
__global__ void k_hist(const int* __restrict__ dst) {
    int i4 = (blockIdx.x * blockDim.x + threadIdx.x) * 4;
    if (i4 + 3 < N_EDGES) {
        int4 d = *(const int4*)(dst + i4);
        atomicAdd(&d_count[d.x], 1);
        atomicAdd(&d_count[d.y], 1);
        atomicAdd(&d_count[d.z], 1);
        atomicAdd(&d_count[d.w], 1);
    } else {
        for (int i = i4; i < N_EDGES; i++) atomicAdd(&d_count[dst[i]], 1);
    }
}

// ---------------- K4: single-block exclusive scan ----------------
__global__ void k_scan() {
    __shared__ int wsum[32];
    int tid = threadIdx.x;
    int lane = tid & 31, wid = tid >> 5;
    int running = 0;
    if (tid == 0) d_offsets[0] = 0;
    for (int b = 0; b < N_NODES; b += 4096) {
        int i0 = b + tid * 4;
        int v0 = 0, v1 = 0, v2 = 0, v3 = 0;
        if (i0 + 3 < N_NODES) {
            int4 v = *(const int4*)&d_count[i0];
            v0 = v.x; v1 = v.y; v2 = v.z; v3 = v.w;
        } else {
            if (i0 + 0 < N_NODES) v0 = d_count[i0 + 0];
            if (i0 + 1 < N_NODES) v1 = d_count[i0 + 1];
            if (i0 + 2 < N_NODES) v2 = d_count[i0 + 2];
            if (i0 + 3 < N_NODES) v3 = d_count[i0 + 3];
        }
        int p0 = v0, p1 = p0 + v1, p2 = p1 + v2, p3 = p2 + v3;
        int x = p3;
        #pragma unroll
        for (int o = 1; o < 32; o <<= 1) {
            int t = __shfl_up_sync(0xffffffffu, x, o);
            if (lane >= o) x += t;
        }
        if (lane == 31) wsum[wid] = x;
        __syncthreads();
        if (wid == 0) {
            int y = wsum[lane];
            #pragma unroll
            for (int o = 1; o < 32; o <<= 1) {
                int t = __shfl_up_sync(0xffffffffu, y, o);
                if (lane >= o) y += t;
            }
            wsum[lane] = y;
        }
        __syncthreads();
        int warpoff = (wid > 0) ? wsum[wid - 1] : 0;
        int bs = running + warpoff + (x - p3);
        if (i0 + 0 < N_NODES) d_offsets[i0 + 1] = bs + p0;
        if (i0 + 1 < N_NODES) d_offsets[i0 + 2] = bs + p1;
        if (i0 + 2 < N_NODES) d_offsets[i0 + 3] = bs + p2;
        if (i0 + 3 < N_NODES) d_offsets[i0 + 4] = bs + p3;
        int tot = wsum[31];
        __syncthreads();
        running += tot;
    }
}

// ---------------- K6: edge logits + inline CSR fill ----------------
__global__ void k_edge_e(const float* __restrict__ edge_inputs,
                         const int* __restrict__ src,
                         const int* __restrict__ dst) {
    __shared__ float sweh[64];
    if (threadIdx.x < 64) sweh[threadIdx.x] = d_weh[threadIdx.x];
    __syncthreads();

    int e = blockIdx.x * blockDim.x + threadIdx.x;
    if (e >= N_EDGES) return;

    int s = src[e];
    int d = dst[e];
    float4 as = *(const float4*)(d_asrc + s * 4);
    float4 ad = *(const float4*)(d_adst + d * 4);

    float ae[4] = {0.f, 0.f, 0.f, 0.f};
    const float* ep = edge_inputs + (size_t)e * 16;
    #pragma unroll
    for (int kq = 0; kq < 4; kq++) {
        float4 ev = *(const float4*)(ep + kq * 4);
        float efs[4] = {ev.x, ev.y, ev.z, ev.w};
        #pragma unroll
        for (int kk = 0; kk < 4; kk++) {
            int k = kq * 4 + kk;
            #pragma unroll
            for (int h = 0; h < 4; h++) ae[h] += efs[kk] * sweh[k * 4 + h];
        }
    }

    float av[4] = {as.x, as.y, as.z, as.w};
    float dv[4] = {ad.x, ad.y, ad.z, ad.w};
    float res[4];
    #pragma unroll
    for (int h = 0; h < 4; h++) {
        float v = av[h] + dv[h] + ae[h];
        res[h] = (v > 0.f) ? v : NEG_SLOPE * v;
    }

    int p = d_offsets[d] + atomicAdd(&d_count2[d], 1);
    d_pe[p] = make_float4(res[0], res[1], res[2], res[3]);
    d_ps[p] = s;
}

// ---------------- K7: warp-per-node single-pass softmax + aggregate --------
__global__ void k_aggregate(float* __restrict__ out) {
    int warp = (blockIdx.x * blockDim.x + threadIdx.x) >> 5;
    int lane = threadIdx.x & 31;
    if (warp >= N_NODES) return;
    int n = warp;

    int begin = d_offsets[n];
    int deg = d_offsets[n + 1] - begin;
    if (deg == 0) return;

    int hl = lane >> 3;
    float s0 = 0.f, s1 = 0.f, s2 = 0.f, s3 = 0.f;
    float acc0 = 0.f, acc1 = 0.f, acc2 = 0.f, acc3 = 0.f;

    for (int b = 0; b < deg; b += 32) {
        int j = b + lane;
        float4 w4 = make_float4(0.f, 0.f, 0.f, 0.f);
        int sn = 0;
        if (j < deg) {
            float4 ev = d_pe[begin + j];
            sn = d_ps[begin + j];
            w4.x = __expf(ev.x);
            w4.y = __expf(ev.y);
            w4.z = __expf(ev.z);
            w4.w = __expf(ev.w);
        }
        s0 += w4.x; s1 += w4.y; s2 += w4.z; s3 += w4.w;
        int cnt = min(32, deg - b);
        #pragma unroll 4
        for (int k = 0; k < cnt; k++) {
            float wx = __shfl_sync(0xffffffffu, w4.x, k);
            float wy = __shfl_sync(0xffffffffu, w4.y, k);
            float wz = __shfl_sync(0xffffffffu, w4.z, k);
            float ww = __shfl_sync(0xffffffffu, w4.w, k);
            int snk = __shfl_sync(0xffffffffu, sn, k);
            float w = (hl < 2) ? (hl == 0 ? wx : wy) : (hl == 2 ? wz : ww);
            uint2 hv = *(const uint2*)(d_feat_h + (size_t)snk * 128 + lane * 4);
            float2 f0 = __half22float2(*(__half2*)&hv.x);
            float2 f1 = __half22float2(*(__half2*)&hv.y);
            acc0 += f0.x * w;
            acc1 += f0.y * w;
            acc2 += f1.x * w;
            acc3 += f1.y * w;
        }
    }
    #pragma unroll
    for (int o = 16; o > 0; o >>= 1) {
        s0 += __shfl_xor_sync(0xffffffffu, s0, o);
        s1 += __shfl_xor_sync(0xffffffffu, s1, o);
        s2 += __shfl_xor_sync(0xffffffffu, s2, o);
        s3 += __shfl_xor_sync(0xffffffffu, s3, o);
    }
    float s = (hl < 2) ? (hl == 0 ? s0 : s1) : (hl == 2 ? s2 : s3);
    float inv = 1.f / s;

    float4* op = (float4*)(out + (size_t)n * 128 + lane * 4);
    float4 ov = *op;  // residual + bias from GEMM epilogue
    ov.x += acc0 * inv; ov.y += acc1 * inv;
    ov.z += acc2 * inv; ov.w += acc3 * inv;
    *op = ov;
}

// ---------------------------------------------------------------------------
extern "C" void kernel_launch(void* const* d_in, const int* in_sizes, int n_in,
                              void* d_out, int out_size) {
    const float* node_inputs = (const float*)d_in[0];
    const float* edge_inputs = (const float*)d_in[1];
    const int*   src         = (const int*)d_in[2];
    const int*   dst         = (const int*)d_in[3];
    const float* W_fc        = (const float*)d_in[4];
    const float* attn_src_p  = (const float*)d_in[5];
    const float* attn_dst_p  = (const float*)d_in[6];
    const float* W_edge      = (const float*)d_in[7];
    const float* attn_edge_p = (const float*)d_in[8];
    const float* W_res       = (const float*)d_in[9];
    const float* bias_p      = (const float*)d_in[10];
    float* out = (float*)d_out;

    cudaFuncSetAttribute(k_gemm_bf, cudaFuncAttributeMaxDynamicSharedMemorySize,
                         GEMM_SMEM);

    k_init<<<256, 256>>>();
    k_weh<<<1, 64>>>(W_edge, attn_edge_p);
    k_bsplit<<<64, 256>>>(W_fc, W_res);
    k_gemm_bf<<<GEMM_GRID, 512, GEMM_SMEM>>>(
        node_inputs, out, bias_p, attn_src_p, attn_dst_p, N_NODES);
    k_hist<<<(N_EDGES / 4 + 255) / 256, 256>>>(dst);
    k_scan<<<1, 1024>>>();
    k_edge_e<<<(N_EDGES + 255) / 256, 256>>>(edge_inputs, src, dst);
    k_aggregate<<<(N_NODES * 32 + 255) / 256, 256>>>(out);
}

// round 8
// speedup vs baseline: 1.7200x; 1.0117x over previous
#include <cuda_runtime.h>
#include <cuda_fp16.h>
#include <cuda_bf16.h>
#include <cstdint>

// ---------------------------------------------------------------------------
// GATConv GB300 (sm_103): N=100000, E=1600000, H=4, D=32
//   KS   setup: B fragments (bf16 hi/lo interleaved uint4) + w_eh + zero counters
//   K1   PERSISTENT 512-thread mma.sync bf16 GEMM (3-term split):
//        feat(fp16) / out(+bias); a_src/a_dst fused in epilogue
//   K3   histogram count[dst]
//   K4   exclusive scan -> offsets
//   K6   edge logits (exp'd) + inline CSR fill -> {exp4},{src} in CSR order
//   K7   warp-per-node single-pass softmax + fp16 gather-aggregate
// ---------------------------------------------------------------------------

#define N_NODES 100000
#define N_EDGES 1600000
#define NEG_SLOPE 0.2f
#define NT_TILES ((N_NODES + 63) / 64)
#define GEMM_GRID 148

__device__ __align__(16) __half d_feat_h[N_NODES * 128];
__device__ __align__(16) float  d_asrc[N_NODES * 4];
__device__ __align__(16) float  d_adst[N_NODES * 4];
__device__ __align__(16) float4 d_pe[N_EDGES];    // exp'd per-head weights
__device__ __align__(16) int    d_ps[N_EDGES];
__device__ __align__(16) float  d_weh[64];        // [k=16][h=4]
__device__ __align__(16) uint4  d_Bf[8192];       // [kt8][ntg32][lane32] {bh0,bh1,bl0,bl1}
__device__ __align__(16) int    d_count[N_NODES + 4];
__device__ __align__(16) int    d_count2[N_NODES];
__device__ __align__(16) int    d_offsets[N_NODES + 1];

// ---------------- helpers ----------------
__device__ __forceinline__ uint32_t smem_to_u32(const void* p) {
    uint32_t a;
    asm("{ .reg .u64 t; cvta.to.shared.u64 t, %1; cvt.u32.u64 %0, t; }"
        : "=r"(a) : "l"(p));
    return a;
}
__device__ __forceinline__ float bfr(float x) {
    return __bfloat162float(__float2bfloat16(x));
}
__device__ __forceinline__ uint32_t pbf2(float a, float b) {
    uint16_t ua = __bfloat16_as_ushort(__float2bfloat16(a));
    uint16_t ub = __bfloat16_as_ushort(__float2bfloat16(b));
    return (uint32_t)ua | ((uint32_t)ub << 16);
}
__device__ __forceinline__ void ldsm4(uint32_t* a, uint32_t addr) {
    asm volatile("ldmatrix.sync.aligned.m8n8.x4.shared.b16 {%0,%1,%2,%3}, [%4];"
        : "=r"(a[0]), "=r"(a[1]), "=r"(a[2]), "=r"(a[3]) : "r"(addr));
}
__device__ __forceinline__ void mma_bf16(float* c, const uint32_t* a,
                                         uint32_t b0, uint32_t b1) {
    asm volatile(
        "mma.sync.aligned.m16n8k16.row.col.f32.bf16.bf16.f32 "
        "{%0,%1,%2,%3}, {%4,%5,%6,%7}, {%8,%9}, {%0,%1,%2,%3};"
        : "+f"(c[0]), "+f"(c[1]), "+f"(c[2]), "+f"(c[3])
        : "r"(a[0]), "r"(a[1]), "r"(a[2]), "r"(a[3]), "r"(b0), "r"(b1));
}

// ---------------- KS: fused setup ----------------
// blocks 0..31  : B fragment split (8192 uint4 entries)
// blocks 32..127: zero counters; block 32 warps 0-1 also compute w_eh
__global__ void k_setup(const float* __restrict__ W_fc,
                        const float* __restrict__ W_res,
                        const float* __restrict__ W_edge,
                        const float* __restrict__ attn_edge) {
    int bid = blockIdx.x, tid = threadIdx.x;
    if (bid < 32) {
        int i = bid * 256 + tid;           // 0..8191
        int lane = i & 31, ntg = (i >> 5) & 31, kt = i >> 10;
        int n = ntg * 8 + (lane >> 2);
        int kb = kt * 16 + (lane & 3) * 2;
        float w[4];
        #pragma unroll
        for (int j = 0; j < 4; j++) {
            int k = kb + (j >> 1) * 8 + (j & 1);
            w[j] = (n < 128) ? W_fc[k * 128 + n] : W_res[k * 128 + n - 128];
        }
        uint4 o;
        o.x = pbf2(w[0], w[1]);
        o.y = pbf2(w[2], w[3]);
        o.z = pbf2(w[0] - bfr(w[0]), w[1] - bfr(w[1]));
        o.w = pbf2(w[2] - bfr(w[2]), w[3] - bfr(w[3]));
        d_Bf[i] = o;
    } else {
        if (bid == 32 && tid < 64) {
            int k = tid >> 2, h = tid & 3;
            float s = 0.f;
            #pragma unroll
            for (int d = 0; d < 32; d++)
                s += W_edge[k * 128 + h * 32 + d] * attn_edge[h * 32 + d];
            d_weh[k * 4 + h] = s;
        }
        int total = (N_NODES + 4) + N_NODES;
        for (int i = (bid - 32) * 256 + tid; i < total; i += 96 * 256) {
            if (i < N_NODES + 4) d_count[i] = 0;
            else d_count2[i - (N_NODES + 4)] = 0;
        }
    }
}

// ---------------- K1: persistent 512-thread bf16x3 mma GEMM ----------------
// smem: [0,131072) B frags (uint4 interleaved); [131072,196608) A tiles
#define SMEM_A_OFF 131072
#define GEMM_SMEM  196608

__global__ __launch_bounds__(512, 1)
void k_gemm_bf(const float* __restrict__ A, float* __restrict__ out,
               const float* __restrict__ bias,
               const float* __restrict__ attn_src,
               const float* __restrict__ attn_dst, int M) {
    extern __shared__ char sm[];
    uint32_t sb = smem_to_u32(sm);
    int tid = threadIdx.x, wid = tid >> 5, lane = tid & 31;
    int warp_m = wid & 1, warp_n = wid >> 1;   // warp_n 0..7

    // copy B fragments once (128 KB)
    {
        const uint4* g = (const uint4*)d_Bf;
        uint4* s = (uint4*)sm;
        #pragma unroll
        for (int j = 0; j < 16; j++) s[j * 512 + tid] = g[j * 512 + tid];
    }

    int r = tid >> 3, cq = tid & 7;        // A fill: 16 floats per thread
    float4 a_st[4];

    auto load_regs = [&](int tile) {
        int grow = tile * 64 + r;
        if (grow < M) {
            const float4* ap = (const float4*)(A + (size_t)grow * 128 + cq * 16);
            #pragma unroll
            for (int q = 0; q < 4; q++) a_st[q] = __ldg(ap + q);
        } else {
            #pragma unroll
            for (int q = 0; q < 4; q++) a_st[q] = make_float4(0.f, 0.f, 0.f, 0.f);
        }
    };
    auto store_stage = [&](int buf) {
        char* hb = sm + SMEM_A_OFF + (buf * 2 + 0) * 16384 + r * 256;
        char* lb = sm + SMEM_A_OFF + (buf * 2 + 1) * 16384 + r * 256;
        int sw = r & 7;
        #pragma unroll
        for (int cc = 0; cc < 2; cc++) {
            float xs[8] = {a_st[cc*2].x, a_st[cc*2].y, a_st[cc*2].z, a_st[cc*2].w,
                           a_st[cc*2+1].x, a_st[cc*2+1].y, a_st[cc*2+1].z, a_st[cc*2+1].w};
            uint32_t hw[4], lw[4];
            #pragma unroll
            for (int p = 0; p < 4; p++) {
                float x0 = xs[p*2], x1 = xs[p*2+1];
                float h0 = bfr(x0), h1 = bfr(x1);
                hw[p] = pbf2(x0, x1);
                lw[p] = pbf2(x0 - h0, x1 - h1);
            }
            int phys = (cq * 2 + cc) ^ sw;
            *(uint4*)(hb + phys * 16) = make_uint4(hw[0], hw[1], hw[2], hw[3]);
            *(uint4*)(lb + phys * 16) = make_uint4(lw[0], lw[1], lw[2], lw[3]);
        }
    };

    const uint4* B4 = (const uint4*)sm;
    int rl = lane & 15, cl = lane >> 4;
    int lr = lane >> 2, lc = (lane & 3) * 2;

    int tile = blockIdx.x;
    if (tile < NT_TILES) load_regs(tile);
    store_stage(0);
    __syncthreads();
    int buf = 0;

    for (; tile < NT_TILES; tile += GEMM_GRID) {
        int nxt = tile + GEMM_GRID;
        bool hn = nxt < NT_TILES;
        if (hn) load_regs(nxt);

        float acc[2][4][4];
        #pragma unroll
        for (int a = 0; a < 2; a++)
            #pragma unroll
            for (int b = 0; b < 4; b++)
                #pragma unroll
                for (int q = 0; q < 4; q++) acc[a][b][q] = 0.f;

        uint32_t aH = sb + SMEM_A_OFF + (buf * 2) * 16384;
        uint32_t aL = aH + 16384;

        #pragma unroll
        for (int kt = 0; kt < 8; kt++) {
            uint32_t ah[2][4], al[2][4];
            #pragma unroll
            for (int mt = 0; mt < 2; mt++) {
                int rr = warp_m * 32 + mt * 16 + rl;
                int c = kt * 2 + cl;
                uint32_t off = (uint32_t)(rr * 256 + ((c ^ (rr & 7)) << 4));
                ldsm4(ah[mt], aH + off);
                ldsm4(al[mt], aL + off);
            }
            #pragma unroll
            for (int nt = 0; nt < 4; nt++) {
                uint4 b = B4[(kt * 32 + warp_n * 4 + nt) * 32 + lane];
                #pragma unroll
                for (int mt = 0; mt < 2; mt++) {
                    mma_bf16(acc[mt][nt], ah[mt], b.x, b.y);
                    mma_bf16(acc[mt][nt], al[mt], b.x, b.y);
                    mma_bf16(acc[mt][nt], ah[mt], b.z, b.w);
                }
            }
        }

        if (hn) store_stage(buf ^ 1);

        // ---- epilogue: warp covers rows warp_m*32..+32, cols warp_n*32..+32
        int row0 = tile * 64;
        bool is_feat = (warp_n < 4);
        #pragma unroll
        for (int mt = 0; mt < 2; mt++) {
            int r0g = row0 + warp_m * 32 + mt * 16 + lr;
            #pragma unroll
            for (int nt = 0; nt < 4; nt++) {
                int col = warp_n * 32 + nt * 8 + lc;
                float* c = acc[mt][nt];
                if (is_feat) {
                    if (r0g < M)
                        *(__half2*)(d_feat_h + (size_t)r0g * 128 + col) =
                            __floats2half2_rn(c[0], c[1]);
                    if (r0g + 8 < M)
                        *(__half2*)(d_feat_h + (size_t)(r0g + 8) * 128 + col) =
                            __floats2half2_rn(c[2], c[3]);
                } else {
                    int oc = col - 128;
                    float2 bz = *(const float2*)(bias + oc);
                    if (r0g < M)
                        *(float2*)(out + (size_t)r0g * 128 + oc) =
                            make_float2(c[0] + bz.x, c[1] + bz.y);
                    if (r0g + 8 < M)
                        *(float2*)(out + (size_t)(r0g + 8) * 128 + oc) =
                            make_float2(c[2] + bz.x, c[3] + bz.y);
                }
            }
            if (is_feat) {
                int head = warp_n;            // this warp's 32 cols = one head
                float ps0 = 0.f, ps1 = 0.f, pd0 = 0.f, pd1 = 0.f;
                #pragma unroll
                for (int nt = 0; nt < 4; nt++) {
                    int cih = nt * 8 + lc;
                    float s0 = __ldg(attn_src + head * 32 + cih);
                    float s1 = __ldg(attn_src + head * 32 + cih + 1);
                    float e0 = __ldg(attn_dst + head * 32 + cih);
                    float e1 = __ldg(attn_dst + head * 32 + cih + 1);
                    float* c = acc[mt][nt];
                    ps0 += c[0] * s0 + c[1] * s1;
                    ps1 += c[2] * s0 + c[3] * s1;
                    pd0 += c[0] * e0 + c[1] * e1;
                    pd1 += c[2] * e0 + c[3] * e1;
                }
                #pragma unroll
                for (int o = 1; o < 4; o <<= 1) {
                    ps0 += __shfl_xor_sync(0xffffffffu, ps0, o);
                    ps1 += __shfl_xor_sync(0xffffffffu, ps1, o);
                    pd0 += __shfl_xor_sync(0xffffffffu, pd0, o);
                    pd1 += __shfl_xor_sync(0xffffffffu, pd1, o);
                }
                if ((lane & 3) == 0) {
                    if (r0g < M) {
                        d_asrc[r0g * 4 + head] = ps0;
                        d_adst[r0g * 4 + head] = pd0;
                    }
                    if (r0g + 8 < M) {
                        d_asrc[(r0g + 8) * 4 + head] = ps1;
                        d_adst[(r0g + 8) * 4 + head] = pd1;
                    }
                }
            }
        }
        __syncthreads();
        buf ^= 1;
    }
}

// ---------------- K3: histogram ----------------
__global__ void k_hist(const int* __restrict__ dst) {
    int i4 = (blockIdx.x * blockDim.x + threadIdx.x) * 4;
    if (i4 + 3 < N_EDGES) {
        int4 d = *(const int4*)(dst + i4);
        atomicAdd(&d_count[d.x], 1);
        atomicAdd(&d_count[d.y], 1);
        atomicAdd(&d_count[d.z], 1);
        atomicAdd(&d_count[d.w], 1);
    } else {
        for (int i = i4; i < N_EDGES; i++) atomicAdd(&d_count[dst[i]], 1);
    }
}

// ---------------- K4: single-block exclusive scan ----------------
__global__ void k_scan() {
    __shared__ int wsum[32];
    int tid = threadIdx.x;
    int lane = tid & 31, wid = tid >> 5;
    int running = 0;
    if (tid == 0) d_offsets[0] = 0;
    for (int b = 0; b < N_NODES; b += 4096) {
        int i0 = b + tid * 4;
        int v0 = 0, v1 = 0, v2 = 0, v3 = 0;
        if (i0 + 3 < N_NODES) {
            int4 v = *(const int4*)&d_count[i0];
            v0 = v.x; v1 = v.y; v2 = v.z; v3 = v.w;
        } else {
            if (i0 + 0 < N_NODES) v0 = d_count[i0 + 0];
            if (i0 + 1 < N_NODES) v1 = d_count[i0 + 1];
            if (i0 + 2 < N_NODES) v2 = d_count[i0 + 2];
            if (i0 + 3 < N_NODES) v3 = d_count[i0 + 3];
        }
        int p0 = v0, p1 = p0 + v1, p2 = p1 + v2, p3 = p2 + v3;
        int x = p3;
        #pragma unroll
        for (int o = 1; o < 32; o <<= 1) {
            int t = __shfl_up_sync(0xffffffffu, x, o);
            if (lane >= o) x += t;
        }
        if (lane == 31) wsum[wid] = x;
        __syncthreads();
        if (wid == 0) {
            int y = wsum[lane];
            #pragma unroll
            for (int o = 1; o < 32; o <<= 1) {
                int t = __shfl_up_sync(0xffffffffu, y, o);
                if (lane >= o) y += t;
            }
            wsum[lane] = y;
        }
        __syncthreads();
        int warpoff = (wid > 0) ? wsum[wid - 1] : 0;
        int bs = running + warpoff + (x - p3);
        if (i0 + 0 < N_NODES) d_offsets[i0 + 1] = bs + p0;
        if (i0 + 1 < N_NODES) d_offsets[i0 + 2] = bs + p1;
        if (i0 + 2 < N_NODES) d_offsets[i0 + 3] = bs + p2;
        if (i0 + 3 < N_NODES) d_offsets[i0 + 4] = bs + p3;
        int tot = wsum[31];
        __syncthreads();
        running += tot;
    }
}

// ---------------- K6: edge logits (exp'd) + inline CSR fill ----------------
__global__ void k_edge_e(const float* __restrict__ edge_inputs,
                         const int* __restrict__ src,
                         const int* __restrict__ dst) {
    __shared__ float sweh[64];
    if (threadIdx.x < 64) sweh[threadIdx.x] = d_weh[threadIdx.x];
    __syncthreads();

    int e = blockIdx.x * blockDim.x + threadIdx.x;
    if (e >= N_EDGES) return;

    int s = src[e];
    int d = dst[e];
    float4 as = *(const float4*)(d_asrc + s * 4);
    float4 ad = *(const float4*)(d_adst + d * 4);

    float ae[4] = {0.f, 0.f, 0.f, 0.f};
    const float* ep = edge_inputs + (size_t)e * 16;
    #pragma unroll
    for (int kq = 0; kq < 4; kq++) {
        float4 ev = *(const float4*)(ep + kq * 4);
        float efs[4] = {ev.x, ev.y, ev.z, ev.w};
        #pragma unroll
        for (int kk = 0; kk < 4; kk++) {
            int k = kq * 4 + kk;
            #pragma unroll
            for (int h = 0; h < 4; h++) ae[h] += efs[kk] * sweh[k * 4 + h];
        }
    }

    float av[4] = {as.x, as.y, as.z, as.w};
    float dv[4] = {ad.x, ad.y, ad.z, ad.w};
    float res[4];
    #pragma unroll
    for (int h = 0; h < 4; h++) {
        float v = av[h] + dv[h] + ae[h];
        float t = (v > 0.f) ? v : NEG_SLOPE * v;
        res[h] = __expf(t);
    }

    int p = d_offsets[d] + atomicAdd(&d_count2[d], 1);
    d_pe[p] = make_float4(res[0], res[1], res[2], res[3]);
    d_ps[p] = s;
}

// ---------------- K7: warp-per-node softmax + aggregate --------------------
__global__ void k_aggregate(float* __restrict__ out) {
    int warp = (blockIdx.x * blockDim.x + threadIdx.x) >> 5;
    int lane = threadIdx.x & 31;
    if (warp >= N_NODES) return;
    int n = warp;

    int begin = d_offsets[n];
    int deg = d_offsets[n + 1] - begin;
    if (deg == 0) return;

    int hl = lane >> 3;
    float s0 = 0.f, s1 = 0.f, s2 = 0.f, s3 = 0.f;
    float acc0 = 0.f, acc1 = 0.f, acc2 = 0.f, acc3 = 0.f;

    for (int b = 0; b < deg; b += 32) {
        int j = b + lane;
        float4 w4 = make_float4(0.f, 0.f, 0.f, 0.f);
        int sn = 0;
        if (j < deg) {
            w4 = d_pe[begin + j];          // already exp'd
            sn = d_ps[begin + j];
        }
        s0 += w4.x; s1 += w4.y; s2 += w4.z; s3 += w4.w;
        int cnt = min(32, deg - b);
        #pragma unroll 4
        for (int k = 0; k < cnt; k++) {
            float wx = __shfl_sync(0xffffffffu, w4.x, k);
            float wy = __shfl_sync(0xffffffffu, w4.y, k);
            float wz = __shfl_sync(0xffffffffu, w4.z, k);
            float ww = __shfl_sync(0xffffffffu, w4.w, k);
            int snk = __shfl_sync(0xffffffffu, sn, k);
            float w = (hl < 2) ? (hl == 0 ? wx : wy) : (hl == 2 ? wz : ww);
            uint2 hv = *(const uint2*)(d_feat_h + (size_t)snk * 128 + lane * 4);
            float2 f0 = __half22float2(*(__half2*)&hv.x);
            float2 f1 = __half22float2(*(__half2*)&hv.y);
            acc0 += f0.x * w;
            acc1 += f0.y * w;
            acc2 += f1.x * w;
            acc3 += f1.y * w;
        }
    }
    #pragma unroll
    for (int o = 16; o > 0; o >>= 1) {
        s0 += __shfl_xor_sync(0xffffffffu, s0, o);
        s1 += __shfl_xor_sync(0xffffffffu, s1, o);
        s2 += __shfl_xor_sync(0xffffffffu, s2, o);
        s3 += __shfl_xor_sync(0xffffffffu, s3, o);
    }
    float s = (hl < 2) ? (hl == 0 ? s0 : s1) : (hl == 2 ? s2 : s3);
    float inv = 1.f / s;

    float4* op = (float4*)(out + (size_t)n * 128 + lane * 4);
    float4 ov = *op;  // residual + bias from GEMM epilogue
    ov.x += acc0 * inv; ov.y += acc1 * inv;
    ov.z += acc2 * inv; ov.w += acc3 * inv;
    *op = ov;
}

// ---------------------------------------------------------------------------
extern "C" void kernel_launch(void* const* d_in, const int* in_sizes, int n_in,
                              void* d_out, int out_size) {
    const float* node_inputs = (const float*)d_in[0];
    const float* edge_inputs = (const float*)d_in[1];
    const int*   src         = (const int*)d_in[2];
    const int*   dst         = (const int*)d_in[3];
    const float* W_fc        = (const float*)d_in[4];
    const float* attn_src_p  = (const float*)d_in[5];
    const float* attn_dst_p  = (const float*)d_in[6];
    const float* W_edge      = (const float*)d_in[7];
    const float* attn_edge_p = (const float*)d_in[8];
    const float* W_res       = (const float*)d_in[9];
    const float* bias_p      = (const float*)d_in[10];
    float* out = (float*)d_out;

    cudaFuncSetAttribute(k_gemm_bf, cudaFuncAttributeMaxDynamicSharedMemorySize,
                         GEMM_SMEM);

    k_setup<<<128, 256>>>(W_fc, W_res, W_edge, attn_edge_p);
    k_gemm_bf<<<GEMM_GRID, 512, GEMM_SMEM>>>(
        node_inputs, out, bias_p, attn_src_p, attn_dst_p, N_NODES);
    k_hist<<<(N_EDGES / 4 + 255) / 256, 256>>>(dst);
    k_scan<<<1, 1024>>>();
    k_edge_e<<<(N_EDGES + 255) / 256, 256>>>(edge_inputs, src, dst);
    k_aggregate<<<(N_NODES * 32 + 255) / 256, 256>>>(out);
}

// round 9
// speedup vs baseline: 1.9454x; 1.1311x over previous
#include <cuda_runtime.h>
#include <cuda_fp16.h>
#include <cuda_bf16.h>
#include <cstdint>

// ---------------------------------------------------------------------------
// GATConv GB300 (sm_103): N=100000, E=1600000, H=4, D=32
//   KS   setup: B fragments + w_eh + zero counters + scan sentinels
//   K1   PERSISTENT 512-thread mma.sync bf16 GEMM (3-term split):
//        feat(fp16) / out(+bias); a_src/a_dst fused in epilogue
//   K3   histogram count[dst]
//   K4   MULTI-BLOCK chained exclusive scan -> offsets (25 blocks)
//   K6   edge logits (exp'd) + inline CSR fill -> {exp4},{src} in CSR order
//   K7   warp-per-node single-pass softmax + fp16 gather-aggregate
// ---------------------------------------------------------------------------

#define N_NODES 100000
#define N_EDGES 1600000
#define NEG_SLOPE 0.2f
#define NT_TILES ((N_NODES + 63) / 64)
#define GEMM_GRID 148
#define SCAN_BLOCKS 25          // 25 * 4096 = 102400 >= N_NODES

__device__ __align__(16) __half d_feat_h[N_NODES * 128];
__device__ __align__(16) float  d_asrc[N_NODES * 4];
__device__ __align__(16) float  d_adst[N_NODES * 4];
__device__ __align__(16) float4 d_pe[N_EDGES];    // exp'd per-head weights
__device__ __align__(16) int    d_ps[N_EDGES];
__device__ __align__(16) float  d_weh[64];        // [k=16][h=4]
__device__ __align__(16) uint4  d_Bf[8192];       // [kt8][ntg32][lane32] {bh0,bh1,bl0,bl1}
__device__ __align__(16) int    d_count[N_NODES + 4];
__device__ __align__(16) int    d_count2[N_NODES];
__device__ __align__(16) int    d_offsets[N_NODES + 1];
__device__ int d_scan_val[SCAN_BLOCKS];           // inclusive prefix through block b (-1 = not ready)

// ---------------- helpers ----------------
__device__ __forceinline__ uint32_t smem_to_u32(const void* p) {
    uint32_t a;
    asm("{ .reg .u64 t; cvta.to.shared.u64 t, %1; cvt.u32.u64 %0, t; }"
        : "=r"(a) : "l"(p));
    return a;
}
__device__ __forceinline__ float bfr(float x) {
    return __bfloat162float(__float2bfloat16(x));
}
__device__ __forceinline__ uint32_t pbf2(float a, float b) {
    uint16_t ua = __bfloat16_as_ushort(__float2bfloat16(a));
    uint16_t ub = __bfloat16_as_ushort(__float2bfloat16(b));
    return (uint32_t)ua | ((uint32_t)ub << 16);
}
__device__ __forceinline__ void ldsm4(uint32_t* a, uint32_t addr) {
    asm volatile("ldmatrix.sync.aligned.m8n8.x4.shared.b16 {%0,%1,%2,%3}, [%4];"
        : "=r"(a[0]), "=r"(a[1]), "=r"(a[2]), "=r"(a[3]) : "r"(addr));
}
__device__ __forceinline__ void mma_bf16(float* c, const uint32_t* a,
                                         uint32_t b0, uint32_t b1) {
    asm volatile(
        "mma.sync.aligned.m16n8k16.row.col.f32.bf16.bf16.f32 "
        "{%0,%1,%2,%3}, {%4,%5,%6,%7}, {%8,%9}, {%0,%1,%2,%3};"
        : "+f"(c[0]), "+f"(c[1]), "+f"(c[2]), "+f"(c[3])
        : "r"(a[0]), "r"(a[1]), "r"(a[2]), "r"(a[3]), "r"(b0), "r"(b1));
}

// ---------------- KS: fused setup ----------------
__global__ void k_setup(const float* __restrict__ W_fc,
                        const float* __restrict__ W_res,
                        const float* __restrict__ W_edge,
                        const float* __restrict__ attn_edge) {
    int bid = blockIdx.x, tid = threadIdx.x;
    if (bid < 32) {
        int i = bid * 256 + tid;           // 0..8191
        int lane = i & 31, ntg = (i >> 5) & 31, kt = i >> 10;
        int n = ntg * 8 + (lane >> 2);
        int kb = kt * 16 + (lane & 3) * 2;
        float w[4];
        #pragma unroll
        for (int j = 0; j < 4; j++) {
            int k = kb + (j >> 1) * 8 + (j & 1);
            w[j] = (n < 128) ? W_fc[k * 128 + n] : W_res[k * 128 + n - 128];
        }
        uint4 o;
        o.x = pbf2(w[0], w[1]);
        o.y = pbf2(w[2], w[3]);
        o.z = pbf2(w[0] - bfr(w[0]), w[1] - bfr(w[1]));
        o.w = pbf2(w[2] - bfr(w[2]), w[3] - bfr(w[3]));
        d_Bf[i] = o;
    } else {
        if (bid == 32 && tid < 64) {
            int k = tid >> 2, h = tid & 3;
            float s = 0.f;
            #pragma unroll
            for (int d = 0; d < 32; d++)
                s += W_edge[k * 128 + h * 32 + d] * attn_edge[h * 32 + d];
            d_weh[k * 4 + h] = s;
        }
        if (bid == 33 && tid < SCAN_BLOCKS) d_scan_val[tid] = -1;
        int total = (N_NODES + 4) + N_NODES;
        for (int i = (bid - 32) * 256 + tid; i < total; i += 96 * 256) {
            if (i < N_NODES + 4) d_count[i] = 0;
            else d_count2[i - (N_NODES + 4)] = 0;
        }
    }
}

// ---------------- K1: persistent 512-thread bf16x3 mma GEMM ----------------
#define SMEM_A_OFF 131072
#define GEMM_SMEM  196608

__global__ __launch_bounds__(512, 1)
void k_gemm_bf(const float* __restrict__ A, float* __restrict__ out,
               const float* __restrict__ bias,
               const float* __restrict__ attn_src,
               const float* __restrict__ attn_dst, int M) {
    extern __shared__ char sm[];
    uint32_t sb = smem_to_u32(sm);
    int tid = threadIdx.x, wid = tid >> 5, lane = tid & 31;
    int warp_m = wid & 1, warp_n = wid >> 1;   // warp_n 0..7

    // copy B fragments once (128 KB)
    {
        const uint4* g = (const uint4*)d_Bf;
        uint4* s = (uint4*)sm;
        #pragma unroll
        for (int j = 0; j < 16; j++) s[j * 512 + tid] = g[j * 512 + tid];
    }

    int r = tid >> 3, cq = tid & 7;        // A fill: 16 floats per thread
    float4 a_st[4];

    auto load_regs = [&](int tile) {
        int grow = tile * 64 + r;
        if (grow < M) {
            const float4* ap = (const float4*)(A + (size_t)grow * 128 + cq * 16);
            #pragma unroll
            for (int q = 0; q < 4; q++) a_st[q] = __ldg(ap + q);
        } else {
            #pragma unroll
            for (int q = 0; q < 4; q++) a_st[q] = make_float4(0.f, 0.f, 0.f, 0.f);
        }
    };
    auto store_stage = [&](int buf) {
        char* hb = sm + SMEM_A_OFF + (buf * 2 + 0) * 16384 + r * 256;
        char* lb = sm + SMEM_A_OFF + (buf * 2 + 1) * 16384 + r * 256;
        int sw = r & 7;
        #pragma unroll
        for (int cc = 0; cc < 2; cc++) {
            float xs[8] = {a_st[cc*2].x, a_st[cc*2].y, a_st[cc*2].z, a_st[cc*2].w,
                           a_st[cc*2+1].x, a_st[cc*2+1].y, a_st[cc*2+1].z, a_st[cc*2+1].w};
            uint32_t hw[4], lw[4];
            #pragma unroll
            for (int p = 0; p < 4; p++) {
                float x0 = xs[p*2], x1 = xs[p*2+1];
                float h0 = bfr(x0), h1 = bfr(x1);
                hw[p] = pbf2(x0, x1);
                lw[p] = pbf2(x0 - h0, x1 - h1);
            }
            int phys = (cq * 2 + cc) ^ sw;
            *(uint4*)(hb + phys * 16) = make_uint4(hw[0], hw[1], hw[2], hw[3]);
            *(uint4*)(lb + phys * 16) = make_uint4(lw[0], lw[1], lw[2], lw[3]);
        }
    };

    const uint4* B4 = (const uint4*)sm;
    int rl = lane & 15, cl = lane >> 4;
    int lr = lane >> 2, lc = (lane & 3) * 2;

    int tile = blockIdx.x;
    if (tile < NT_TILES) load_regs(tile);
    store_stage(0);
    __syncthreads();
    int buf = 0;

    for (; tile < NT_TILES; tile += GEMM_GRID) {
        int nxt = tile + GEMM_GRID;
        bool hn = nxt < NT_TILES;
        if (hn) load_regs(nxt);

        float acc[2][4][4];
        #pragma unroll
        for (int a = 0; a < 2; a++)
            #pragma unroll
            for (int b = 0; b < 4; b++)
                #pragma unroll
                for (int q = 0; q < 4; q++) acc[a][b][q] = 0.f;

        uint32_t aH = sb + SMEM_A_OFF + (buf * 2) * 16384;
        uint32_t aL = aH + 16384;

        #pragma unroll
        for (int kt = 0; kt < 8; kt++) {
            uint32_t ah[2][4], al[2][4];
            #pragma unroll
            for (int mt = 0; mt < 2; mt++) {
                int rr = warp_m * 32 + mt * 16 + rl;
                int c = kt * 2 + cl;
                uint32_t off = (uint32_t)(rr * 256 + ((c ^ (rr & 7)) << 4));
                ldsm4(ah[mt], aH + off);
                ldsm4(al[mt], aL + off);
            }
            #pragma unroll
            for (int nt = 0; nt < 4; nt++) {
                uint4 b = B4[(kt * 32 + warp_n * 4 + nt) * 32 + lane];
                #pragma unroll
                for (int mt = 0; mt < 2; mt++) {
                    mma_bf16(acc[mt][nt], ah[mt], b.x, b.y);
                    mma_bf16(acc[mt][nt], al[mt], b.x, b.y);
                    mma_bf16(acc[mt][nt], ah[mt], b.z, b.w);
                }
            }
        }

        if (hn) store_stage(buf ^ 1);

        // ---- epilogue
        int row0 = tile * 64;
        bool is_feat = (warp_n < 4);
        #pragma unroll
        for (int mt = 0; mt < 2; mt++) {
            int r0g = row0 + warp_m * 32 + mt * 16 + lr;
            #pragma unroll
            for (int nt = 0; nt < 4; nt++) {
                int col = warp_n * 32 + nt * 8 + lc;
                float* c = acc[mt][nt];
                if (is_feat) {
                    if (r0g < M)
                        *(__half2*)(d_feat_h + (size_t)r0g * 128 + col) =
                            __floats2half2_rn(c[0], c[1]);
                    if (r0g + 8 < M)
                        *(__half2*)(d_feat_h + (size_t)(r0g + 8) * 128 + col) =
                            __floats2half2_rn(c[2], c[3]);
                } else {
                    int oc = col - 128;
                    float2 bz = *(const float2*)(bias + oc);
                    if (r0g < M)
                        *(float2*)(out + (size_t)r0g * 128 + oc) =
                            make_float2(c[0] + bz.x, c[1] + bz.y);
                    if (r0g + 8 < M)
                        *(float2*)(out + (size_t)(r0g + 8) * 128 + oc) =
                            make_float2(c[2] + bz.x, c[3] + bz.y);
                }
            }
            if (is_feat) {
                int head = warp_n;
                float ps0 = 0.f, ps1 = 0.f, pd0 = 0.f, pd1 = 0.f;
                #pragma unroll
                for (int nt = 0; nt < 4; nt++) {
                    int cih = nt * 8 + lc;
                    float s0 = __ldg(attn_src + head * 32 + cih);
                    float s1 = __ldg(attn_src + head * 32 + cih + 1);
                    float e0 = __ldg(attn_dst + head * 32 + cih);
                    float e1 = __ldg(attn_dst + head * 32 + cih + 1);
                    float* c = acc[mt][nt];
                    ps0 += c[0] * s0 + c[1] * s1;
                    ps1 += c[2] * s0 + c[3] * s1;
                    pd0 += c[0] * e0 + c[1] * e1;
                    pd1 += c[2] * e0 + c[3] * e1;
                }
                #pragma unroll
                for (int o = 1; o < 4; o <<= 1) {
                    ps0 += __shfl_xor_sync(0xffffffffu, ps0, o);
                    ps1 += __shfl_xor_sync(0xffffffffu, ps1, o);
                    pd0 += __shfl_xor_sync(0xffffffffu, pd0, o);
                    pd1 += __shfl_xor_sync(0xffffffffu, pd1, o);
                }
                if ((lane & 3) == 0) {
                    if (r0g < M) {
                        d_asrc[r0g * 4 + head] = ps0;
                        d_adst[r0g * 4 + head] = pd0;
                    }
                    if (r0g + 8 < M) {
                        d_asrc[(r0g + 8) * 4 + head] = ps1;
                        d_adst[(r0g + 8) * 4 + head] = pd1;
                    }
                }
            }
        }
        __syncthreads();
        buf ^= 1;
    }
}

// ---------------- K3: histogram ----------------
__global__ void k_hist(const int* __restrict__ dst) {
    int i4 = (blockIdx.x * blockDim.x + threadIdx.x) * 4;
    if (i4 + 3 < N_EDGES) {
        int4 d = *(const int4*)(dst + i4);
        atomicAdd(&d_count[d.x], 1);
        atomicAdd(&d_count[d.y], 1);
        atomicAdd(&d_count[d.z], 1);
        atomicAdd(&d_count[d.w], 1);
    } else {
        for (int i = i4; i < N_EDGES; i++) atomicAdd(&d_count[dst[i]], 1);
    }
}

// ---------------- K4: chained multi-block exclusive scan -------------------
// 25 blocks x 1024 threads x 4 elems; blocks all resident -> lookback safe
__global__ __launch_bounds__(1024, 1)
void k_scan_mb() {
    __shared__ int wsum[32];
    __shared__ int s_prefix;
    int bid = blockIdx.x, tid = threadIdx.x;
    int lane = tid & 31, wid = tid >> 5;

    int i0 = bid * 4096 + tid * 4;
    int v0 = 0, v1 = 0, v2 = 0, v3 = 0;
    if (i0 + 3 < N_NODES) {
        int4 v = *(const int4*)&d_count[i0];
        v0 = v.x; v1 = v.y; v2 = v.z; v3 = v.w;
    } else {
        if (i0 + 0 < N_NODES) v0 = d_count[i0 + 0];
        if (i0 + 1 < N_NODES) v1 = d_count[i0 + 1];
        if (i0 + 2 < N_NODES) v2 = d_count[i0 + 2];
        if (i0 + 3 < N_NODES) v3 = d_count[i0 + 3];
    }
    int p0 = v0, p1 = p0 + v1, p2 = p1 + v2, p3 = p2 + v3;
    int x = p3;
    #pragma unroll
    for (int o = 1; o < 32; o <<= 1) {
        int t = __shfl_up_sync(0xffffffffu, x, o);
        if (lane >= o) x += t;
    }
    if (lane == 31) wsum[wid] = x;
    __syncthreads();
    if (wid == 0) {
        int y = wsum[lane];
        #pragma unroll
        for (int o = 1; o < 32; o <<= 1) {
            int t = __shfl_up_sync(0xffffffffu, y, o);
            if (lane >= o) y += t;
        }
        wsum[lane] = y;
    }
    __syncthreads();
    int warpoff = (wid > 0) ? wsum[wid - 1] : 0;
    int texcl = x - p3;                 // exclusive within block
    int block_total = wsum[31];

    // chained lookback
    if (tid == 0) {
        int prefix = 0;
        if (bid > 0) {
            while ((prefix = atomicAdd(&d_scan_val[bid - 1], 0)) == -1) {}
        }
        atomicExch(&d_scan_val[bid], prefix + block_total);
        s_prefix = prefix;
        if (bid == 0) d_offsets[0] = 0;
    }
    __syncthreads();
    int bs = s_prefix + warpoff + texcl;

    if (i0 + 0 < N_NODES) d_offsets[i0 + 1] = bs + p0;
    if (i0 + 1 < N_NODES) d_offsets[i0 + 2] = bs + p1;
    if (i0 + 2 < N_NODES) d_offsets[i0 + 3] = bs + p2;
    if (i0 + 3 < N_NODES) d_offsets[i0 + 4] = bs + p3;
}

// ---------------- K6: edge logits (exp'd) + inline CSR fill ----------------
__global__ void k_edge_e(const float* __restrict__ edge_inputs,
                         const int* __restrict__ src,
                         const int* __restrict__ dst) {
    __shared__ float sweh[64];
    if (threadIdx.x < 64) sweh[threadIdx.x] = d_weh[threadIdx.x];
    __syncthreads();

    int e = blockIdx.x * blockDim.x + threadIdx.x;
    if (e >= N_EDGES) return;

    int s = src[e];
    int d = dst[e];
    float4 as = *(const float4*)(d_asrc + s * 4);
    float4 ad = *(const float4*)(d_adst + d * 4);

    float ae[4] = {0.f, 0.f, 0.f, 0.f};
    const float* ep = edge_inputs + (size_t)e * 16;
    #pragma unroll
    for (int kq = 0; kq < 4; kq++) {
        float4 ev = *(const float4*)(ep + kq * 4);
        float efs[4] = {ev.x, ev.y, ev.z, ev.w};
        #pragma unroll
        for (int kk = 0; kk < 4; kk++) {
            int k = kq * 4 + kk;
            #pragma unroll
            for (int h = 0; h < 4; h++) ae[h] += efs[kk] * sweh[k * 4 + h];
        }
    }

    float av[4] = {as.x, as.y, as.z, as.w};
    float dv[4] = {ad.x, ad.y, ad.z, ad.w};
    float res[4];
    #pragma unroll
    for (int h = 0; h < 4; h++) {
        float v = av[h] + dv[h] + ae[h];
        float t = (v > 0.f) ? v : NEG_SLOPE * v;
        res[h] = __expf(t);
    }

    int p = d_offsets[d] + atomicAdd(&d_count2[d], 1);
    d_pe[p] = make_float4(res[0], res[1], res[2], res[3]);
    d_ps[p] = s;
}

// ---------------- K7: warp-per-node softmax + aggregate --------------------
__global__ void k_aggregate(float* __restrict__ out) {
    int warp = (blockIdx.x * blockDim.x + threadIdx.x) >> 5;
    int lane = threadIdx.x & 31;
    if (warp >= N_NODES) return;
    int n = warp;

    int begin = d_offsets[n];
    int deg = d_offsets[n + 1] - begin;
    if (deg == 0) return;

    int hl = lane >> 3;
    float s0 = 0.f, s1 = 0.f, s2 = 0.f, s3 = 0.f;
    float acc0 = 0.f, acc1 = 0.f, acc2 = 0.f, acc3 = 0.f;

    for (int b = 0; b < deg; b += 32) {
        int j = b + lane;
        float4 w4 = make_float4(0.f, 0.f, 0.f, 0.f);
        int sn = 0;
        if (j < deg) {
            w4 = d_pe[begin + j];          // already exp'd
            sn = d_ps[begin + j];
        }
        s0 += w4.x; s1 += w4.y; s2 += w4.z; s3 += w4.w;
        int cnt = min(32, deg - b);
        #pragma unroll 4
        for (int k = 0; k < cnt; k++) {
            float wx = __shfl_sync(0xffffffffu, w4.x, k);
            float wy = __shfl_sync(0xffffffffu, w4.y, k);
            float wz = __shfl_sync(0xffffffffu, w4.z, k);
            float ww = __shfl_sync(0xffffffffu, w4.w, k);
            int snk = __shfl_sync(0xffffffffu, sn, k);
            float w = (hl < 2) ? (hl == 0 ? wx : wy) : (hl == 2 ? wz : ww);
            uint2 hv = *(const uint2*)(d_feat_h + (size_t)snk * 128 + lane * 4);
            float2 f0 = __half22float2(*(__half2*)&hv.x);
            float2 f1 = __half22float2(*(__half2*)&hv.y);
            acc0 += f0.x * w;
            acc1 += f0.y * w;
            acc2 += f1.x * w;
            acc3 += f1.y * w;
        }
    }
    #pragma unroll
    for (int o = 16; o > 0; o >>= 1) {
        s0 += __shfl_xor_sync(0xffffffffu, s0, o);
        s1 += __shfl_xor_sync(0xffffffffu, s1, o);
        s2 += __shfl_xor_sync(0xffffffffu, s2, o);
        s3 += __shfl_xor_sync(0xffffffffu, s3, o);
    }
    float s = (hl < 2) ? (hl == 0 ? s0 : s1) : (hl == 2 ? s2 : s3);
    float inv = 1.f / s;

    float4* op = (float4*)(out + (size_t)n * 128 + lane * 4);
    float4 ov = *op;  // residual + bias from GEMM epilogue
    ov.x += acc0 * inv; ov.y += acc1 * inv;
    ov.z += acc2 * inv; ov.w += acc3 * inv;
    *op = ov;
}

// ---------------------------------------------------------------------------
extern "C" void kernel_launch(void* const* d_in, const int* in_sizes, int n_in,
                              void* d_out, int out_size) {
    const float* node_inputs = (const float*)d_in[0];
    const float* edge_inputs = (const float*)d_in[1];
    const int*   src         = (const int*)d_in[2];
    const int*   dst         = (const int*)d_in[3];
    const float* W_fc        = (const float*)d_in[4];
    const float* attn_src_p  = (const float*)d_in[5];
    const float* attn_dst_p  = (const float*)d_in[6];
    const float* W_edge      = (const float*)d_in[7];
    const float* attn_edge_p = (const float*)d_in[8];
    const float* W_res       = (const float*)d_in[9];
    const float* bias_p      = (const float*)d_in[10];
    float* out = (float*)d_out;

    cudaFuncSetAttribute(k_gemm_bf, cudaFuncAttributeMaxDynamicSharedMemorySize,
                         GEMM_SMEM);

    k_setup<<<128, 256>>>(W_fc, W_res, W_edge, attn_edge_p);
    k_gemm_bf<<<GEMM_GRID, 512, GEMM_SMEM>>>(
        node_inputs, out, bias_p, attn_src_p, attn_dst_p, N_NODES);
    k_hist<<<(N_EDGES / 4 + 255) / 256, 256>>>(dst);
    k_scan_mb<<<SCAN_BLOCKS, 1024>>>();
    k_edge_e<<<(N_EDGES + 255) / 256, 256>>>(edge_inputs, src, dst);
    k_aggregate<<<(N_NODES * 32 + 255) / 256, 256>>>(out);
}

// round 10
// speedup vs baseline: 2.0364x; 1.0468x over previous
#include <cuda_runtime.h>
#include <cuda_fp16.h>
#include <cuda_bf16.h>
#include <cstdint>

// ---------------------------------------------------------------------------
// GATConv GB300 (sm_103): N=100000, E=1600000, H=4, D=32
//   KS   setup: B fragments + w_eh + zero counters + scan sentinels
//   s1:  K3 histogram, K4 chained multi-block scan   (overlapped with K1)
//   s0:  K1 persistent 512-thread mma.sync bf16 GEMM (3-term split)
//   K6   edge logits (exp'd, fp16 payload) + inline CSR fill
//   K7   warp-per-node single-pass softmax + fp16 gather-aggregate
// ---------------------------------------------------------------------------

#define N_NODES 100000
#define N_EDGES 1600000
#define NEG_SLOPE 0.2f
#define NT_TILES ((N_NODES + 63) / 64)
#define GEMM_GRID 148
#define SCAN_BLOCKS 25          // 25 * 4096 = 102400 >= N_NODES

__device__ __align__(16) __half d_feat_h[N_NODES * 128];
__device__ __align__(16) float  d_asrc[N_NODES * 4];
__device__ __align__(16) float  d_adst[N_NODES * 4];
__device__ __align__(16) uint2  d_peh[N_EDGES];   // exp'd weights as half4
__device__ __align__(16) int    d_ps[N_EDGES];
__device__ __align__(16) float  d_weh[64];        // [k=16][h=4]
__device__ __align__(16) uint4  d_Bf[8192];       // [kt8][ntg32][lane32]
__device__ __align__(16) int    d_count[N_NODES + 4];
__device__ __align__(16) int    d_count2[N_NODES];
__device__ __align__(16) int    d_offsets[N_NODES + 1];
__device__ int d_scan_val[SCAN_BLOCKS];

// ---------------- helpers ----------------
__device__ __forceinline__ uint32_t smem_to_u32(const void* p) {
    uint32_t a;
    asm("{ .reg .u64 t; cvta.to.shared.u64 t, %1; cvt.u32.u64 %0, t; }"
        : "=r"(a) : "l"(p));
    return a;
}
__device__ __forceinline__ float bfr(float x) {
    return __bfloat162float(__float2bfloat16(x));
}
__device__ __forceinline__ uint32_t pbf2(float a, float b) {
    uint16_t ua = __bfloat16_as_ushort(__float2bfloat16(a));
    uint16_t ub = __bfloat16_as_ushort(__float2bfloat16(b));
    return (uint32_t)ua | ((uint32_t)ub << 16);
}
__device__ __forceinline__ void ldsm4(uint32_t* a, uint32_t addr) {
    asm volatile("ldmatrix.sync.aligned.m8n8.x4.shared.b16 {%0,%1,%2,%3}, [%4];"
        : "=r"(a[0]), "=r"(a[1]), "=r"(a[2]), "=r"(a[3]) : "r"(addr));
}
__device__ __forceinline__ void mma_bf16(float* c, const uint32_t* a,
                                         uint32_t b0, uint32_t b1) {
    asm volatile(
        "mma.sync.aligned.m16n8k16.row.col.f32.bf16.bf16.f32 "
        "{%0,%1,%2,%3}, {%4,%5,%6,%7}, {%8,%9}, {%0,%1,%2,%3};"
        : "+f"(c[0]), "+f"(c[1]), "+f"(c[2]), "+f"(c[3])
        : "r"(a[0]), "r"(a[1]), "r"(a[2]), "r"(a[3]), "r"(b0), "r"(b1));
}

// ---------------- KS: fused setup ----------------
__global__ void k_setup(const float* __restrict__ W_fc,
                        const float* __restrict__ W_res,
                        const float* __restrict__ W_edge,
                        const float* __restrict__ attn_edge) {
    int bid = blockIdx.x, tid = threadIdx.x;
    if (bid < 32) {
        int i = bid * 256 + tid;           // 0..8191
        int lane = i & 31, ntg = (i >> 5) & 31, kt = i >> 10;
        int n = ntg * 8 + (lane >> 2);
        int kb = kt * 16 + (lane & 3) * 2;
        float w[4];
        #pragma unroll
        for (int j = 0; j < 4; j++) {
            int k = kb + (j >> 1) * 8 + (j & 1);
            w[j] = (n < 128) ? W_fc[k * 128 + n] : W_res[k * 128 + n - 128];
        }
        uint4 o;
        o.x = pbf2(w[0], w[1]);
        o.y = pbf2(w[2], w[3]);
        o.z = pbf2(w[0] - bfr(w[0]), w[1] - bfr(w[1]));
        o.w = pbf2(w[2] - bfr(w[2]), w[3] - bfr(w[3]));
        d_Bf[i] = o;
    } else {
        if (bid == 32 && tid < 64) {
            int k = tid >> 2, h = tid & 3;
            float s = 0.f;
            #pragma unroll
            for (int d = 0; d < 32; d++)
                s += W_edge[k * 128 + h * 32 + d] * attn_edge[h * 32 + d];
            d_weh[k * 4 + h] = s;
        }
        if (bid == 33 && tid < SCAN_BLOCKS) d_scan_val[tid] = -1;
        int total = (N_NODES + 4) + N_NODES;
        for (int i = (bid - 32) * 256 + tid; i < total; i += 96 * 256) {
            if (i < N_NODES + 4) d_count[i] = 0;
            else d_count2[i - (N_NODES + 4)] = 0;
        }
    }
}

// ---------------- K1: persistent 512-thread bf16x3 mma GEMM ----------------
#define SMEM_A_OFF 131072
#define GEMM_SMEM  196608

__global__ __launch_bounds__(512, 1)
void k_gemm_bf(const float* __restrict__ A, float* __restrict__ out,
               const float* __restrict__ bias,
               const float* __restrict__ attn_src,
               const float* __restrict__ attn_dst, int M) {
    extern __shared__ char sm[];
    uint32_t sb = smem_to_u32(sm);
    int tid = threadIdx.x, wid = tid >> 5, lane = tid & 31;
    int warp_m = wid & 1, warp_n = wid >> 1;   // warp_n 0..7

    // copy B fragments once (128 KB)
    {
        const uint4* g = (const uint4*)d_Bf;
        uint4* s = (uint4*)sm;
        #pragma unroll
        for (int j = 0; j < 16; j++) s[j * 512 + tid] = g[j * 512 + tid];
    }

    int r = tid >> 3, cq = tid & 7;        // A fill: 16 floats per thread
    float4 a_st[4];

    auto load_regs = [&](int tile) {
        int grow = tile * 64 + r;
        if (grow < M) {
            const float4* ap = (const float4*)(A + (size_t)grow * 128 + cq * 16);
            #pragma unroll
            for (int q = 0; q < 4; q++) a_st[q] = __ldg(ap + q);
        } else {
            #pragma unroll
            for (int q = 0; q < 4; q++) a_st[q] = make_float4(0.f, 0.f, 0.f, 0.f);
        }
    };
    auto store_stage = [&](int buf) {
        char* hb = sm + SMEM_A_OFF + (buf * 2 + 0) * 16384 + r * 256;
        char* lb = sm + SMEM_A_OFF + (buf * 2 + 1) * 16384 + r * 256;
        int sw = r & 7;
        #pragma unroll
        for (int cc = 0; cc < 2; cc++) {
            float xs[8] = {a_st[cc*2].x, a_st[cc*2].y, a_st[cc*2].z, a_st[cc*2].w,
                           a_st[cc*2+1].x, a_st[cc*2+1].y, a_st[cc*2+1].z, a_st[cc*2+1].w};
            uint32_t hw[4], lw[4];
            #pragma unroll
            for (int p = 0; p < 4; p++) {
                float x0 = xs[p*2], x1 = xs[p*2+1];
                float h0 = bfr(x0), h1 = bfr(x1);
                hw[p] = pbf2(x0, x1);
                lw[p] = pbf2(x0 - h0, x1 - h1);
            }
            int phys = (cq * 2 + cc) ^ sw;
            *(uint4*)(hb + phys * 16) = make_uint4(hw[0], hw[1], hw[2], hw[3]);
            *(uint4*)(lb + phys * 16) = make_uint4(lw[0], lw[1], lw[2], lw[3]);
        }
    };

    const uint4* B4 = (const uint4*)sm;
    int rl = lane & 15, cl = lane >> 4;
    int lr = lane >> 2, lc = (lane & 3) * 2;

    int tile = blockIdx.x;
    if (tile < NT_TILES) load_regs(tile);
    store_stage(0);
    __syncthreads();
    int buf = 0;

    for (; tile < NT_TILES; tile += GEMM_GRID) {
        int nxt = tile + GEMM_GRID;
        bool hn = nxt < NT_TILES;
        if (hn) load_regs(nxt);

        float acc[2][4][4];
        #pragma unroll
        for (int a = 0; a < 2; a++)
            #pragma unroll
            for (int b = 0; b < 4; b++)
                #pragma unroll
                for (int q = 0; q < 4; q++) acc[a][b][q] = 0.f;

        uint32_t aH = sb + SMEM_A_OFF + (buf * 2) * 16384;
        uint32_t aL = aH + 16384;

        #pragma unroll
        for (int kt = 0; kt < 8; kt++) {
            uint32_t ah[2][4], al[2][4];
            #pragma unroll
            for (int mt = 0; mt < 2; mt++) {
                int rr = warp_m * 32 + mt * 16 + rl;
                int c = kt * 2 + cl;
                uint32_t off = (uint32_t)(rr * 256 + ((c ^ (rr & 7)) << 4));
                ldsm4(ah[mt], aH + off);
                ldsm4(al[mt], aL + off);
            }
            #pragma unroll
            for (int nt = 0; nt < 4; nt++) {
                uint4 b = B4[(kt * 32 + warp_n * 4 + nt) * 32 + lane];
                #pragma unroll
                for (int mt = 0; mt < 2; mt++) {
                    mma_bf16(acc[mt][nt], ah[mt], b.x, b.y);
                    mma_bf16(acc[mt][nt], al[mt], b.x, b.y);
                    mma_bf16(acc[mt][nt], ah[mt], b.z, b.w);
                }
            }
        }

        if (hn) store_stage(buf ^ 1);

        // ---- epilogue
        int row0 = tile * 64;
        bool is_feat = (warp_n < 4);
        #pragma unroll
        for (int mt = 0; mt < 2; mt++) {
            int r0g = row0 + warp_m * 32 + mt * 16 + lr;
            #pragma unroll
            for (int nt = 0; nt < 4; nt++) {
                int col = warp_n * 32 + nt * 8 + lc;
                float* c = acc[mt][nt];
                if (is_feat) {
                    if (r0g < M)
                        *(__half2*)(d_feat_h + (size_t)r0g * 128 + col) =
                            __floats2half2_rn(c[0], c[1]);
                    if (r0g + 8 < M)
                        *(__half2*)(d_feat_h + (size_t)(r0g + 8) * 128 + col) =
                            __floats2half2_rn(c[2], c[3]);
                } else {
                    int oc = col - 128;
                    float2 bz = *(const float2*)(bias + oc);
                    if (r0g < M)
                        *(float2*)(out + (size_t)r0g * 128 + oc) =
                            make_float2(c[0] + bz.x, c[1] + bz.y);
                    if (r0g + 8 < M)
                        *(float2*)(out + (size_t)(r0g + 8) * 128 + oc) =
                            make_float2(c[2] + bz.x, c[3] + bz.y);
                }
            }
            if (is_feat) {
                int head = warp_n;
                float ps0 = 0.f, ps1 = 0.f, pd0 = 0.f, pd1 = 0.f;
                #pragma unroll
                for (int nt = 0; nt < 4; nt++) {
                    int cih = nt * 8 + lc;
                    float s0 = __ldg(attn_src + head * 32 + cih);
                    float s1 = __ldg(attn_src + head * 32 + cih + 1);
                    float e0 = __ldg(attn_dst + head * 32 + cih);
                    float e1 = __ldg(attn_dst + head * 32 + cih + 1);
                    float* c = acc[mt][nt];
                    ps0 += c[0] * s0 + c[1] * s1;
                    ps1 += c[2] * s0 + c[3] * s1;
                    pd0 += c[0] * e0 + c[1] * e1;
                    pd1 += c[2] * e0 + c[3] * e1;
                }
                #pragma unroll
                for (int o = 1; o < 4; o <<= 1) {
                    ps0 += __shfl_xor_sync(0xffffffffu, ps0, o);
                    ps1 += __shfl_xor_sync(0xffffffffu, ps1, o);
                    pd0 += __shfl_xor_sync(0xffffffffu, pd0, o);
                    pd1 += __shfl_xor_sync(0xffffffffu, pd1, o);
                }
                if ((lane & 3) == 0) {
                    if (r0g < M) {
                        d_asrc[r0g * 4 + head] = ps0;
                        d_adst[r0g * 4 + head] = pd0;
                    }
                    if (r0g + 8 < M) {
                        d_asrc[(r0g + 8) * 4 + head] = ps1;
                        d_adst[(r0g + 8) * 4 + head] = pd1;
                    }
                }
            }
        }
        __syncthreads();
        buf ^= 1;
    }
}

// ---------------- K3: histogram ----------------
__global__ void k_hist(const int* __restrict__ dst) {
    int i4 = (blockIdx.x * blockDim.x + threadIdx.x) * 4;
    if (i4 + 3 < N_EDGES) {
        int4 d = *(const int4*)(dst + i4);
        atomicAdd(&d_count[d.x], 1);
        atomicAdd(&d_count[d.y], 1);
        atomicAdd(&d_count[d.z], 1);
        atomicAdd(&d_count[d.w], 1);
    } else {
        for (int i = i4; i < N_EDGES; i++) atomicAdd(&d_count[dst[i]], 1);
    }
}

// ---------------- K4: chained multi-block exclusive scan -------------------
__global__ __launch_bounds__(1024, 1)
void k_scan_mb() {
    __shared__ int wsum[32];
    __shared__ int s_prefix;
    int bid = blockIdx.x, tid = threadIdx.x;
    int lane = tid & 31, wid = tid >> 5;

    int i0 = bid * 4096 + tid * 4;
    int v0 = 0, v1 = 0, v2 = 0, v3 = 0;
    if (i0 + 3 < N_NODES) {
        int4 v = *(const int4*)&d_count[i0];
        v0 = v.x; v1 = v.y; v2 = v.z; v3 = v.w;
    } else {
        if (i0 + 0 < N_NODES) v0 = d_count[i0 + 0];
        if (i0 + 1 < N_NODES) v1 = d_count[i0 + 1];
        if (i0 + 2 < N_NODES) v2 = d_count[i0 + 2];
        if (i0 + 3 < N_NODES) v3 = d_count[i0 + 3];
    }
    int p0 = v0, p1 = p0 + v1, p2 = p1 + v2, p3 = p2 + v3;
    int x = p3;
    #pragma unroll
    for (int o = 1; o < 32; o <<= 1) {
        int t = __shfl_up_sync(0xffffffffu, x, o);
        if (lane >= o) x += t;
    }
    if (lane == 31) wsum[wid] = x;
    __syncthreads();
    if (wid == 0) {
        int y = wsum[lane];
        #pragma unroll
        for (int o = 1; o < 32; o <<= 1) {
            int t = __shfl_up_sync(0xffffffffu, y, o);
            if (lane >= o) y += t;
        }
        wsum[lane] = y;
    }
    __syncthreads();
    int warpoff = (wid > 0) ? wsum[wid - 1] : 0;
    int texcl = x - p3;
    int block_total = wsum[31];

    if (tid == 0) {
        int prefix = 0;
        if (bid > 0) {
            while ((prefix = atomicAdd(&d_scan_val[bid - 1], 0)) == -1) {}
        }
        atomicExch(&d_scan_val[bid], prefix + block_total);
        s_prefix = prefix;
        if (bid == 0) d_offsets[0] = 0;
    }
    __syncthreads();
    int bs = s_prefix + warpoff + texcl;

    if (i0 + 0 < N_NODES) d_offsets[i0 + 1] = bs + p0;
    if (i0 + 1 < N_NODES) d_offsets[i0 + 2] = bs + p1;
    if (i0 + 2 < N_NODES) d_offsets[i0 + 3] = bs + p2;
    if (i0 + 3 < N_NODES) d_offsets[i0 + 4] = bs + p3;
}

// ---------------- K6: edge logits (exp'd fp16) + inline CSR fill ------------
__global__ void k_edge_e(const float* __restrict__ edge_inputs,
                         const int* __restrict__ src,
                         const int* __restrict__ dst) {
    __shared__ float sweh[64];
    if (threadIdx.x < 64) sweh[threadIdx.x] = d_weh[threadIdx.x];
    __syncthreads();

    int e = blockIdx.x * blockDim.x + threadIdx.x;
    if (e >= N_EDGES) return;

    int s = src[e];
    int d = dst[e];
    float4 as = *(const float4*)(d_asrc + s * 4);
    float4 ad = *(const float4*)(d_adst + d * 4);

    float ae[4] = {0.f, 0.f, 0.f, 0.f};
    const float* ep = edge_inputs + (size_t)e * 16;
    #pragma unroll
    for (int kq = 0; kq < 4; kq++) {
        float4 ev = *(const float4*)(ep + kq * 4);
        float efs[4] = {ev.x, ev.y, ev.z, ev.w};
        #pragma unroll
        for (int kk = 0; kk < 4; kk++) {
            int k = kq * 4 + kk;
            #pragma unroll
            for (int h = 0; h < 4; h++) ae[h] += efs[kk] * sweh[k * 4 + h];
        }
    }

    float av[4] = {as.x, as.y, as.z, as.w};
    float dv[4] = {ad.x, ad.y, ad.z, ad.w};
    float res[4];
    #pragma unroll
    for (int h = 0; h < 4; h++) {
        float v = av[h] + dv[h] + ae[h];
        float t = (v > 0.f) ? v : NEG_SLOPE * v;
        res[h] = __expf(t);
    }

    int p = d_offsets[d] + atomicAdd(&d_count2[d], 1);
    __half2 h01 = __floats2half2_rn(res[0], res[1]);
    __half2 h23 = __floats2half2_rn(res[2], res[3]);
    d_peh[p] = make_uint2(*(uint32_t*)&h01, *(uint32_t*)&h23);
    d_ps[p] = s;
}

// ---------------- K7: warp-per-node softmax + aggregate --------------------
__global__ void k_aggregate(float* __restrict__ out) {
    int warp = (blockIdx.x * blockDim.x + threadIdx.x) >> 5;
    int lane = threadIdx.x & 31;
    if (warp >= N_NODES) return;
    int n = warp;

    int begin = d_offsets[n];
    int deg = d_offsets[n + 1] - begin;
    if (deg == 0) return;

    int hl = lane >> 3;
    float s0 = 0.f, s1 = 0.f, s2 = 0.f, s3 = 0.f;
    float acc0 = 0.f, acc1 = 0.f, acc2 = 0.f, acc3 = 0.f;

    for (int b = 0; b < deg; b += 32) {
        int j = b + lane;
        uint2 pv = make_uint2(0u, 0u);
        int sn = 0;
        if (j < deg) {
            pv = d_peh[begin + j];
            sn = d_ps[begin + j];
        }
        float2 f01 = __half22float2(*(__half2*)&pv.x);
        float2 f23 = __half22float2(*(__half2*)&pv.y);
        s0 += f01.x; s1 += f01.y; s2 += f23.x; s3 += f23.y;
        int cnt = min(32, deg - b);
        #pragma unroll 4
        for (int k = 0; k < cnt; k++) {
            uint32_t px = __shfl_sync(0xffffffffu, pv.x, k);
            uint32_t py = __shfl_sync(0xffffffffu, pv.y, k);
            int snk = __shfl_sync(0xffffffffu, sn, k);
            uint32_t sel = (hl < 2) ? px : py;
            float2 wf = __half22float2(*(__half2*)&sel);
            float w = (hl & 1) ? wf.y : wf.x;
            uint2 hv = *(const uint2*)(d_feat_h + (size_t)snk * 128 + lane * 4);
            float2 f0 = __half22float2(*(__half2*)&hv.x);
            float2 f1 = __half22float2(*(__half2*)&hv.y);
            acc0 += f0.x * w;
            acc1 += f0.y * w;
            acc2 += f1.x * w;
            acc3 += f1.y * w;
        }
    }
    #pragma unroll
    for (int o = 16; o > 0; o >>= 1) {
        s0 += __shfl_xor_sync(0xffffffffu, s0, o);
        s1 += __shfl_xor_sync(0xffffffffu, s1, o);
        s2 += __shfl_xor_sync(0xffffffffu, s2, o);
        s3 += __shfl_xor_sync(0xffffffffu, s3, o);
    }
    float s = (hl < 2) ? (hl == 0 ? s0 : s1) : (hl == 2 ? s2 : s3);
    float inv = 1.f / s;

    float4* op = (float4*)(out + (size_t)n * 128 + lane * 4);
    float4 ov = *op;  // residual + bias from GEMM epilogue
    ov.x += acc0 * inv; ov.y += acc1 * inv;
    ov.z += acc2 * inv; ov.w += acc3 * inv;
    *op = ov;
}

// ---------------------------------------------------------------------------
extern "C" void kernel_launch(void* const* d_in, const int* in_sizes, int n_in,
                              void* d_out, int out_size) {
    const float* node_inputs = (const float*)d_in[0];
    const float* edge_inputs = (const float*)d_in[1];
    const int*   src         = (const int*)d_in[2];
    const int*   dst         = (const int*)d_in[3];
    const float* W_fc        = (const float*)d_in[4];
    const float* attn_src_p  = (const float*)d_in[5];
    const float* attn_dst_p  = (const float*)d_in[6];
    const float* W_edge      = (const float*)d_in[7];
    const float* attn_edge_p = (const float*)d_in[8];
    const float* W_res       = (const float*)d_in[9];
    const float* bias_p      = (const float*)d_in[10];
    float* out = (float*)d_out;

    static cudaStream_t s1;
    static cudaEvent_t evA, evS;
    static bool inited = false;
    if (!inited) {
        cudaStreamCreateWithFlags(&s1, cudaStreamNonBlocking);
        cudaEventCreateWithFlags(&evA, cudaEventDisableTiming);
        cudaEventCreateWithFlags(&evS, cudaEventDisableTiming);
        cudaFuncSetAttribute(k_gemm_bf,
                             cudaFuncAttributeMaxDynamicSharedMemorySize,
                             GEMM_SMEM);
        inited = true;
    }

    // setup on default stream
    k_setup<<<128, 256>>>(W_fc, W_res, W_edge, attn_edge_p);
    cudaEventRecord(evA, 0);

    // side stream: histogram + scan (independent of GEMM)
    cudaStreamWaitEvent(s1, evA, 0);
    k_hist<<<(N_EDGES / 4 + 255) / 256, 256, 0, s1>>>(dst);
    k_scan_mb<<<SCAN_BLOCKS, 1024, 0, s1>>>();
    cudaEventRecord(evS, s1);

    // main stream: GEMM overlapping with hist/scan
    k_gemm_bf<<<GEMM_GRID, 512, GEMM_SMEM>>>(
        node_inputs, out, bias_p, attn_src_p, attn_dst_p, N_NODES);

    // join, then edge + aggregate
    cudaStreamWaitEvent(0, evS, 0);
    k_edge_e<<<(N_EDGES + 255) / 256, 256>>>(edge_inputs, src, dst);
    k_aggregate<<<(N_NODES * 32 + 255) / 256, 256>>>(out);
}